// round 1
// baseline (speedup 1.0000x reference)
#include <cuda_runtime.h>
#include <cstdint>

#define N_NODES 4096
#define D_FEAT  256
#define N_EDGES 65536

// ------------------------- static device scratch -------------------------
static __device__ float g_sraw[N_EDGES];
static __device__ unsigned g_minb, g_maxb;
static __device__ int   g_deg[N_NODES];
static __device__ int   g_rowptr[N_NODES + 1];
static __device__ int   g_fill[N_NODES];
static __device__ float g_csr_s[N_EDGES];
static __device__ int   g_csr_dst[N_EDGES];
static __device__ int   g_csr_eid[N_EDGES];
static __device__ float g_tot[N_NODES];
static __device__ int   g_cntN[N_NODES];
static __device__ float g_avg[N_NODES];
static __device__ unsigned short g_mem[N_NODES][8];
static __device__ int   g_msz[N_NODES];
static __device__ unsigned long long g_khi[N_NODES], g_klo[N_NODES];
static __device__ unsigned long long g_shi[N_NODES], g_slo[N_NODES];
static __device__ int   g_sidx[N_NODES];
static __device__ unsigned short g_uniq[N_NODES][8];
static __device__ int   g_usz[N_NODES];
static __device__ int   g_U;
static __device__ int   g_n2ucnt[N_NODES], g_n2uptr[N_NODES + 1], g_n2ufill[N_NODES];
static __device__ int   g_n2ulist[N_NODES * 8];
static __device__ int   g_sel[N_NODES];
static __device__ int   g_K;
static __device__ int   g_c2cnt[N_NODES], g_c2ptr[N_NODES + 1], g_c2fill[N_NODES];
static __device__ int   g_c2list[N_NODES * 8];
static __device__ unsigned char g_B[(size_t)N_NODES * N_NODES];   // cluster adj bitmap (16 MB)
static __device__ int   g_rn[N_NODES], g_roff[N_NODES + 1];

// ------------------------- kernels -------------------------

__global__ void k_init() {
    int i = blockIdx.x * blockDim.x + threadIdx.x;
    if (i < N_NODES) {
        g_deg[i] = 0; g_fill[i] = 0;
        g_tot[i] = 0.f; g_cntN[i] = 0;
        g_n2ucnt[i] = 0; g_n2ufill[i] = 0;
        g_c2cnt[i] = 0; g_c2fill[i] = 0;
    }
    if (i == 0) { g_minb = 0x7f800000u; g_maxb = 0u; }
}

// one warp per edge: distance, degree count, block-reduced global min/max
__global__ void k_dist(const float* __restrict__ x, const int* __restrict__ ei) {
    int warp = threadIdx.x >> 5, lane = threadIdx.x & 31;
    int e = blockIdx.x * 8 + warp;
    __shared__ float smin[8], smax[8];
    float sval = __int_as_float(0x7f800000);
    {
        int u = ei[e], v = ei[N_EDGES + e];
        const float* xu = x + (size_t)u * D_FEAT;
        const float* xv = x + (size_t)v * D_FEAT;
        double acc = 0.0;
        #pragma unroll
        for (int i = 0; i < 8; i++) {
            float a = xu[lane + 32 * i], b = xv[lane + 32 * i];
            double d = (double)a - (double)b;
            acc += d * d;
        }
        #pragma unroll
        for (int o = 16; o; o >>= 1) acc += __shfl_down_sync(0xffffffffu, acc, o);
        if (lane == 0) {
            float sf = (float)acc;
            float s = sqrtf(sf + 1e-12f);
            g_sraw[e] = s;
            atomicAdd(&g_deg[u], 1);
            sval = s;
        }
    }
    if (lane == 0) { smin[warp] = sval; smax[warp] = sval; }
    __syncthreads();
    if (threadIdx.x == 0) {
        float mn = smin[0], mx = smax[0];
        #pragma unroll
        for (int i = 1; i < 8; i++) { mn = fminf(mn, smin[i]); mx = fmaxf(mx, smax[i]); }
        atomicMin(&g_minb, __float_as_uint(mn));
        atomicMax(&g_maxb, __float_as_uint(mx));
    }
}

// exclusive scan of a fixed 4096-int array selected by `which`
__global__ void k_scan4096(int which) {
    const int* in; int* out;
    switch (which) {
        case 0:  in = g_deg;    out = g_rowptr;  break;
        case 1:  in = g_n2ucnt; out = g_n2uptr;  break;
        case 2:  in = g_c2cnt;  out = g_c2ptr;   break;
        default: in = g_rn;     out = g_roff;    break;
    }
    __shared__ int sh[1024];
    int t = threadIdx.x;
    int v0 = in[t * 4 + 0], v1 = in[t * 4 + 1], v2 = in[t * 4 + 2], v3 = in[t * 4 + 3];
    int s = v0 + v1 + v2 + v3;
    sh[t] = s; __syncthreads();
    for (int off = 1; off < 1024; off <<= 1) {
        int a = (t >= off) ? sh[t - off] : 0;
        __syncthreads();
        sh[t] += a;
        __syncthreads();
    }
    int pre = t ? sh[t - 1] : 0;
    out[t * 4 + 0] = pre;
    out[t * 4 + 1] = pre + v0;
    out[t * 4 + 2] = pre + v0 + v1;
    out[t * 4 + 3] = pre + v0 + v1 + v2;
    if (t == 1023) out[4096] = sh[1023];
}

__global__ void k_norm_fill(const int* __restrict__ ei) {
    int e = blockIdx.x * 256 + threadIdx.x;
    float mn = __uint_as_float(g_minb), mx = __uint_as_float(g_maxb);
    float s = (g_sraw[e] - mn) / (mx - mn) + 0.5f;
    int u = ei[e], v = ei[N_EDGES + e];
    atomicAdd(&g_tot[u], s); atomicAdd(&g_tot[v], s);
    atomicAdd(&g_cntN[u], 1); atomicAdd(&g_cntN[v], 1);
    int slot = g_rowptr[u] + atomicAdd(&g_fill[u], 1);
    g_csr_s[slot] = s; g_csr_dst[slot] = v; g_csr_eid[slot] = e;
}

__global__ void k_avg() {
    int i = blockIdx.x * blockDim.x + threadIdx.x;
    if (i < N_NODES) g_avg[i] = g_tot[i] / (float)g_cntN[i];
}

// one thread per seed: Prim-style growth replicating fp32 tot accumulation
// and (score, edge-id) argmin tie-break.
__global__ void k_grow() {
    int i = blockIdx.x * blockDim.x + threadIdx.x;
    if (i >= N_NODES) return;
    unsigned short memb[8];
    #pragma unroll
    for (int j = 0; j < 8; j++) memb[j] = 0xFFFF;
    memb[0] = (unsigned short)i;
    int msz = 1; float tot = 0.f;
    const float INF = __int_as_float(0x7f800000);
    while (tot < 3.0f && msz < 8) {
        float bs = INF; int be = 0x7fffffff; int bd = -1;
        for (int mi = 0; mi < msz; mi++) {
            int u = memb[mi];
            int p0 = g_rowptr[u], p1 = g_rowptr[u + 1];
            for (int p = p0; p < p1; p++) {
                int d = g_csr_dst[p];
                bool in = false;
                for (int j = 0; j < msz; j++) if (memb[j] == (unsigned short)d) { in = true; break; }
                if (in) continue;
                float s = g_csr_s[p]; int ee = g_csr_eid[p];
                if (s < bs || (s == bs && ee < be)) { bs = s; be = ee; bd = d; }
            }
        }
        if (bd < 0) break;
        tot += bs;
        int j = msz - 1;
        while (j >= 0 && memb[j] > (unsigned short)bd) { memb[j + 1] = memb[j]; j--; }
        memb[j + 1] = (unsigned short)bd;
        msz++;
    }
    #pragma unroll
    for (int j = 0; j < 8; j++) g_mem[i][j] = memb[j];
    g_msz[i] = msz;
    // 128-bit key: ascending lex order of (8191 - member) == np.unique row order
    unsigned long long hi = 0, lo = 0;
    #pragma unroll
    for (int j = 0; j < 7; j++) {
        unsigned long long k = (j < msz) ? (unsigned long long)(8191u - memb[j]) : 0ull;
        if (j < 4) hi |= k << (48 - 16 * j);
        else       lo |= k << (48 - 16 * (j - 4));
    }
    g_khi[i] = hi; g_klo[i] = lo;
}

// O(n^2) rank sort of 4096 128-bit keys (stable via index tiebreak)
__global__ void k_rank() {
    int i = blockIdx.x * blockDim.x + threadIdx.x;
    if (i >= N_NODES) return;
    unsigned long long hi = g_khi[i], lo = g_klo[i];
    int r = 0;
    for (int j = 0; j < N_NODES; j++) {
        unsigned long long hj = __ldg(&g_khi[j]), lj = __ldg(&g_klo[j]);
        bool less = (hj < hi) || (hj == hi && (lj < lo || (lj == lo && j < i)));
        r += (int)less;
    }
    g_shi[r] = hi; g_slo[r] = lo; g_sidx[r] = i;
}

// dedup adjacent equal keys, compact member lists into g_uniq
__global__ void k_dedup() {
    __shared__ int sh[1024];
    int t = threadIdx.x;
    int fl[4], loc[4];
    int s = 0;
    #pragma unroll
    for (int q = 0; q < 4; q++) {
        int r = t * 4 + q;
        int f = (r == 0) ? 1 : ((g_shi[r] != g_shi[r - 1]) || (g_slo[r] != g_slo[r - 1]));
        fl[q] = f; loc[q] = s; s += f;
    }
    sh[t] = s; __syncthreads();
    for (int off = 1; off < 1024; off <<= 1) {
        int a = (t >= off) ? sh[t - off] : 0;
        __syncthreads();
        sh[t] += a;
        __syncthreads();
    }
    int pre = t ? sh[t - 1] : 0;
    #pragma unroll
    for (int q = 0; q < 4; q++) {
        int r = t * 4 + q;
        if (fl[q]) {
            int pos = pre + loc[q];
            int src = g_sidx[r];
            #pragma unroll
            for (int j = 0; j < 8; j++) g_uniq[pos][j] = g_mem[src][j];
            g_usz[pos] = g_msz[src];
        }
    }
    if (t == 1023) g_U = sh[1023];
}

__global__ void k_n2u_cnt() {
    int u = blockIdx.x * blockDim.x + threadIdx.x;
    if (u >= g_U) return;
    int sz = g_usz[u];
    for (int mi = 0; mi < sz; mi++) atomicAdd(&g_n2ucnt[g_uniq[u][mi]], 1);
}

__global__ void k_n2u_fill() {
    int u = blockIdx.x * blockDim.x + threadIdx.x;
    if (u >= g_U) return;
    int sz = g_usz[u];
    for (int mi = 0; mi < sz; mi++) {
        int m = g_uniq[u][mi];
        int slot = g_n2uptr[m] + atomicAdd(&g_n2ufill[m], 1);
        g_n2ulist[slot] = u;
    }
}

// persistent single-block greedy max-cover with incremental counts
__global__ void k_greedy() {
    __shared__ int s_cnt[N_NODES];
    __shared__ int s_seg[128];
    __shared__ unsigned s_cov[128];
    __shared__ int s_best, s_covTot, s_K, s_nNew;
    __shared__ unsigned short s_newm[8];
    int t = threadIdx.x;
    int U = g_U;
    for (int c = t; c < N_NODES; c += 1024) s_cnt[c] = (c < U) ? g_usz[c] : 0;
    for (int w = t; w < 128; w += 1024) s_cov[w] = 0u;
    if (t == 0) { s_covTot = 0; s_K = 0; }
    __syncthreads();
    int wid = t >> 5, lane = t & 31;
    for (int iter = 0; iter <= N_NODES; iter++) {
        if (s_covTot >= N_NODES) break;
        // 128 segment maxima of key = (cnt<<12)|(4095-c)
        for (int sg = wid; sg < 128; sg += 32) {
            int c = sg * 32 + lane;
            int cc = s_cnt[c];
            int key = (cc > 0) ? ((cc << 12) | (4095 - c)) : 0;
            #pragma unroll
            for (int o = 16; o; o >>= 1) key = max(key, __shfl_down_sync(0xffffffffu, key, o));
            if (lane == 0) s_seg[sg] = key;
        }
        __syncthreads();
        if (wid == 0) {
            int key = max(max(s_seg[lane], s_seg[lane + 32]), max(s_seg[lane + 64], s_seg[lane + 96]));
            #pragma unroll
            for (int o = 16; o; o >>= 1) key = max(key, __shfl_down_sync(0xffffffffu, key, o));
            if (lane == 0) s_best = key;
        }
        __syncthreads();
        if (t == 0) {
            int key = s_best;
            int c = 4095 - (key & 4095);
            int cb = key >> 12;
            g_sel[s_K] = c; s_K++;
            s_covTot += cb;
            int nn = 0;
            int sz = g_usz[c];
            for (int mi = 0; mi < sz; mi++) {
                unsigned short m = g_uniq[c][mi];
                unsigned wv = s_cov[m >> 5];
                if (!((wv >> (m & 31)) & 1u)) {
                    s_cov[m >> 5] = wv | (1u << (m & 31));
                    s_newm[nn++] = m;
                }
            }
            s_nNew = nn;
        }
        __syncthreads();
        int nn = s_nNew;
        for (int mi = 0; mi < nn; mi++) {
            int m = s_newm[mi];
            int b = g_n2uptr[m], en = g_n2uptr[m + 1];
            for (int j = b + t; j < en; j += 1024) atomicSub(&s_cnt[g_n2ulist[j]], 1);
        }
        __syncthreads();
    }
    if (t == 0) g_K = s_K;
}

__global__ void k_c2_cnt() {
    int k = blockIdx.x * blockDim.x + threadIdx.x;
    if (k >= g_K) return;
    int c = g_sel[k];
    int sz = g_usz[c];
    for (int mi = 0; mi < sz; mi++) atomicAdd(&g_c2cnt[g_uniq[c][mi]], 1);
}

__global__ void k_c2_fill() {
    int k = blockIdx.x * blockDim.x + threadIdx.x;
    if (k >= g_K) return;
    int c = g_sel[k];
    int sz = g_usz[c];
    for (int mi = 0; mi < sz; mi++) {
        int m = g_uniq[c][mi];
        int slot = g_c2ptr[m] + atomicAdd(&g_c2fill[m], 1);
        g_c2list[slot] = k;
    }
}

__global__ void k_clearB() {
    int tot = g_K * N_NODES;
    int stride = gridDim.x * blockDim.x;
    for (int i = blockIdx.x * blockDim.x + threadIdx.x; i < tot; i += stride)
        g_B[i] = 0;
}

__global__ void k_markB(const int* __restrict__ ei) {
    int e = blockIdx.x * 256 + threadIdx.x;
    int u = ei[e], v = ei[N_EDGES + e];
    int a0 = g_c2ptr[u], a1 = g_c2ptr[u + 1];
    int b0 = g_c2ptr[v], b1 = g_c2ptr[v + 1];
    for (int p = a0; p < a1; p++) {
        size_t base = (size_t)g_c2list[p] * N_NODES;
        for (int q = b0; q < b1; q++) g_B[base + g_c2list[q]] = 1;
    }
}

__global__ void k_rowcnt() {
    int i = blockIdx.x * blockDim.x + threadIdx.x;
    if (i >= N_NODES) return;
    int K = g_K;
    if (i >= K) { g_rn[i] = 0; return; }
    const unsigned char* row = g_B + (size_t)i * N_NODES;
    int c = 0;
    for (int j = 0; j < K; j++) c += (int)((j != i) && (row[j] != 0));
    g_rn[i] = c;
}

__global__ void k_write_edges(float* __restrict__ out) {
    int i = blockIdx.x * blockDim.x + threadIdx.x;
    int K = g_K;
    if (i >= K) return;
    int nnz = g_roff[K];
    const unsigned char* row = g_B + (size_t)i * N_NODES;
    int p = g_roff[i];
    for (int j = 0; j < K; j++) {
        if (j != i && row[j]) {
            out[p] = (float)i;
            out[nnz + p] = (float)j;
            p++;
        }
    }
}

__global__ void k_xnew(const float* __restrict__ x, float* __restrict__ out) {
    int k = blockIdx.x;
    if (k >= g_K) return;
    int c = g_sel[k];
    int sz = g_usz[c];
    int d = threadIdx.x;
    float acc = 0.f;
    for (int mi = 0; mi < sz; mi++) {
        int m = g_uniq[c][mi];
        acc += g_avg[m] * x[(size_t)m * D_FEAT + d];
    }
    int off = 2 * g_roff[g_K];
    out[off + k * D_FEAT + d] = acc;
}

__global__ void k_zeroSM(float* __restrict__ out) {
    int K = g_K;
    int nnz = g_roff[K];
    int offS = 2 * nnz + K * D_FEAT;
    int tot = 2 * K * N_NODES;
    int stride = gridDim.x * blockDim.x;
    for (int i = blockIdx.x * blockDim.x + threadIdx.x; i < tot; i += stride)
        out[offS + i] = 0.f;
}

__global__ void k_scatterSM(float* __restrict__ out) {
    int t = blockIdx.x * blockDim.x + threadIdx.x;
    int K = g_K;
    if (t >= K) return;
    int nnz = g_roff[K];
    int offS = 2 * nnz + K * D_FEAT;
    int offM = offS + K * N_NODES;
    int c = g_sel[t];
    int sz = g_usz[c];
    for (int mi = 0; mi < sz; mi++) {
        int m = g_uniq[c][mi];
        out[offS + t * N_NODES + m] = 1.0f;
        out[offM + t * N_NODES + m] = g_avg[m];
    }
}

__global__ void k_copyEI(const int* __restrict__ ei, float* __restrict__ out) {
    int i = blockIdx.x * blockDim.x + threadIdx.x;
    if (i >= 2 * N_EDGES) return;
    int K = g_K;
    int off = 2 * g_roff[K] + K * D_FEAT + 2 * K * N_NODES;
    out[off + i] = (float)ei[i];
}

// ------------------------- launch -------------------------
extern "C" void kernel_launch(void* const* d_in, const int* in_sizes, int n_in,
                              void* d_out, int out_size) {
    const float* x  = (const float*)d_in[0];
    const int*   ei = (const int*)d_in[1];
    float*       out = (float*)d_out;
    cudaStream_t st = cudaStreamPerThread;

    k_init     <<<16, 256, 0, st>>>();
    k_dist     <<<N_EDGES / 8, 256, 0, st>>>(x, ei);
    k_scan4096 <<<1, 1024, 0, st>>>(0);            // deg -> rowptr
    k_norm_fill<<<N_EDGES / 256, 256, 0, st>>>(ei);
    k_avg      <<<16, 256, 0, st>>>();
    k_grow     <<<16, 256, 0, st>>>();
    k_rank     <<<16, 256, 0, st>>>();
    k_dedup    <<<1, 1024, 0, st>>>();
    k_n2u_cnt  <<<16, 256, 0, st>>>();
    k_scan4096 <<<1, 1024, 0, st>>>(1);            // n2ucnt -> n2uptr
    k_n2u_fill <<<16, 256, 0, st>>>();
    k_greedy   <<<1, 1024, 0, st>>>();
    k_c2_cnt   <<<16, 256, 0, st>>>();
    k_scan4096 <<<1, 1024, 0, st>>>(2);            // c2cnt -> c2ptr
    k_c2_fill  <<<16, 256, 0, st>>>();
    k_clearB   <<<2048, 256, 0, st>>>();
    k_markB    <<<N_EDGES / 256, 256, 0, st>>>(ei);
    k_rowcnt   <<<16, 256, 0, st>>>();
    k_scan4096 <<<1, 1024, 0, st>>>(3);            // rn -> roff
    k_write_edges<<<16, 256, 0, st>>>(out);
    k_xnew     <<<N_NODES, 256, 0, st>>>(x, out);
    k_zeroSM   <<<2048, 256, 0, st>>>(out);
    k_scatterSM<<<16, 256, 0, st>>>(out);
    k_copyEI   <<<512, 256, 0, st>>>(ei, out);
}

// round 2
// speedup vs baseline: 1.8317x; 1.8317x over previous
#include <cuda_runtime.h>
#include <cstdint>

#define N_NODES 4096
#define D_FEAT  256
#define N_EDGES 65536

// ------------------------- static device scratch -------------------------
static __device__ float g_sraw[N_EDGES];
static __device__ unsigned g_minb, g_maxb;
static __device__ int   g_deg[N_NODES];
static __device__ int   g_rowptr[N_NODES + 1];
static __device__ int   g_fill[N_NODES];
static __device__ unsigned long long g_csr_key[N_EDGES];   // (score_bits<<32)|eid
static __device__ int   g_csr_dst[N_EDGES];
static __device__ float g_tot[N_NODES];
static __device__ int   g_cntN[N_NODES];
static __device__ float g_avg[N_NODES];
static __device__ unsigned short g_mem[N_NODES][8];
static __device__ int   g_msz[N_NODES];
static __device__ unsigned long long g_khi[N_NODES], g_klo[N_NODES];
static __device__ unsigned short g_uniq[N_NODES][8];
static __device__ int   g_usz[N_NODES];
static __device__ int   g_U;
static __device__ int   g_n2ucnt[N_NODES], g_n2uptr[N_NODES + 1], g_n2ufill[N_NODES];
static __device__ int   g_n2ulist[N_NODES * 8];
static __device__ int   g_sel[N_NODES];
static __device__ int   g_K;
static __device__ int   g_c2cnt[N_NODES], g_c2ptr[N_NODES + 1], g_c2fill[N_NODES];
static __device__ int   g_c2list[N_NODES * 8];
static __device__ unsigned char g_B[(size_t)N_NODES * N_NODES];   // cluster adj bitmap
static __device__ int   g_rn[N_NODES], g_roff[N_NODES + 1];

// ------------------------- kernels -------------------------

__global__ void k_init() {
    int i = blockIdx.x * blockDim.x + threadIdx.x;
    if (i < N_NODES) {
        g_deg[i] = 0; g_fill[i] = 0;
        g_tot[i] = 0.f; g_cntN[i] = 0;
        g_n2ucnt[i] = 0; g_n2ufill[i] = 0;
        g_c2cnt[i] = 0; g_c2fill[i] = 0;
    }
    if (i == 0) { g_minb = 0x7f800000u; g_maxb = 0u; }
}

// one warp per edge: distance, degree count, block-reduced global min/max
__global__ void k_dist(const float* __restrict__ x, const int* __restrict__ ei) {
    int warp = threadIdx.x >> 5, lane = threadIdx.x & 31;
    int e = blockIdx.x * 8 + warp;
    __shared__ float smin[8], smax[8];
    float sval = __int_as_float(0x7f800000);
    {
        int u = ei[e], v = ei[N_EDGES + e];
        const float* xu = x + (size_t)u * D_FEAT;
        const float* xv = x + (size_t)v * D_FEAT;
        double acc = 0.0;
        #pragma unroll
        for (int i = 0; i < 8; i++) {
            float a = xu[lane + 32 * i], b = xv[lane + 32 * i];
            double d = (double)a - (double)b;
            acc += d * d;
        }
        #pragma unroll
        for (int o = 16; o; o >>= 1) acc += __shfl_down_sync(0xffffffffu, acc, o);
        if (lane == 0) {
            float sf = (float)acc;
            float s = sqrtf(sf + 1e-12f);
            g_sraw[e] = s;
            atomicAdd(&g_deg[u], 1);
            sval = s;
        }
    }
    if (lane == 0) { smin[warp] = sval; smax[warp] = sval; }
    __syncthreads();
    if (threadIdx.x == 0) {
        float mn = smin[0], mx = smax[0];
        #pragma unroll
        for (int i = 1; i < 8; i++) { mn = fminf(mn, smin[i]); mx = fmaxf(mx, smax[i]); }
        atomicMin(&g_minb, __float_as_uint(mn));
        atomicMax(&g_maxb, __float_as_uint(mx));
    }
}

// exclusive scan of a fixed 4096-int array selected by `which`
__global__ void k_scan4096(int which) {
    const int* in; int* out;
    switch (which) {
        case 0:  in = g_deg;    out = g_rowptr;  break;
        case 1:  in = g_n2ucnt; out = g_n2uptr;  break;
        case 2:  in = g_c2cnt;  out = g_c2ptr;   break;
        default: in = g_rn;     out = g_roff;    break;
    }
    __shared__ int sh[1024];
    int t = threadIdx.x;
    int v0 = in[t * 4 + 0], v1 = in[t * 4 + 1], v2 = in[t * 4 + 2], v3 = in[t * 4 + 3];
    int s = v0 + v1 + v2 + v3;
    sh[t] = s; __syncthreads();
    for (int off = 1; off < 1024; off <<= 1) {
        int a = (t >= off) ? sh[t - off] : 0;
        __syncthreads();
        sh[t] += a;
        __syncthreads();
    }
    int pre = t ? sh[t - 1] : 0;
    out[t * 4 + 0] = pre;
    out[t * 4 + 1] = pre + v0;
    out[t * 4 + 2] = pre + v0 + v1;
    out[t * 4 + 3] = pre + v0 + v1 + v2;
    if (t == 1023) out[4096] = sh[1023];
}

__global__ void k_norm_fill(const int* __restrict__ ei) {
    int e = blockIdx.x * 256 + threadIdx.x;
    float mn = __uint_as_float(g_minb), mx = __uint_as_float(g_maxb);
    float s = (g_sraw[e] - mn) / (mx - mn) + 0.5f;
    int u = ei[e], v = ei[N_EDGES + e];
    atomicAdd(&g_tot[u], s); atomicAdd(&g_tot[v], s);
    atomicAdd(&g_cntN[u], 1); atomicAdd(&g_cntN[v], 1);
    int slot = g_rowptr[u] + atomicAdd(&g_fill[u], 1);
    g_csr_key[slot] = ((unsigned long long)__float_as_uint(s) << 32) | (unsigned)e;
    g_csr_dst[slot] = v;
}

__global__ void k_avg() {
    int i = blockIdx.x * blockDim.x + threadIdx.x;
    if (i < N_NODES) g_avg[i] = g_tot[i] / (float)g_cntN[i];
}

// warp-per-seed Prim-style growth; members register-resident via predicated
// unrolled loops; warp argmin over 64-bit (score,eid) keys.
__global__ void k_grow() {   // <<<512,256>>>
    int wid = threadIdx.x >> 5, lane = threadIdx.x & 31;
    int i = blockIdx.x * 8 + wid;
    unsigned short memb[8];
    #pragma unroll
    for (int j = 0; j < 8; j++) memb[j] = 0xFFFF;
    #pragma unroll
    for (int j = 0; j < 8; j++) if (j == 0) memb[j] = (unsigned short)i;
    int msz = 1; float tot = 0.f;
    while (tot < 3.0f && msz < 8) {
        unsigned long long bk = ~0ull; int bd = -1;
        #pragma unroll
        for (int mi = 0; mi < 7; mi++) {
            if (mi >= msz) break;
            int u = -1;
            #pragma unroll
            for (int j = 0; j < 7; j++) if (j == mi) u = memb[j];
            int p0 = g_rowptr[u], p1 = g_rowptr[u + 1];
            for (int p = p0 + lane; p < p1; p += 32) {
                int d = g_csr_dst[p];
                bool in = false;
                #pragma unroll
                for (int j = 0; j < 7; j++) in |= (j < msz) && (memb[j] == (unsigned short)d);
                if (in) continue;
                unsigned long long key = g_csr_key[p];
                if (key < bk) { bk = key; bd = d; }
            }
        }
        #pragma unroll
        for (int o = 16; o; o >>= 1) {
            unsigned long long ok = __shfl_down_sync(0xffffffffu, bk, o);
            int od = __shfl_down_sync(0xffffffffu, bd, o);
            if (ok < bk) { bk = ok; bd = od; }
        }
        bk = __shfl_sync(0xffffffffu, bk, 0);
        bd = __shfl_sync(0xffffffffu, bd, 0);
        if (bd < 0) break;
        tot += __uint_as_float((unsigned)(bk >> 32));
        // sorted insert (replicated in all lanes, register-resident)
        int pos = 0;
        #pragma unroll
        for (int j = 0; j < 7; j++) pos += (j < msz && memb[j] < (unsigned short)bd);
        #pragma unroll
        for (int j = 6; j >= 0; j--) if (j >= pos && j < msz) memb[j + 1] = memb[j];
        #pragma unroll
        for (int j = 0; j < 8; j++) if (j == pos) memb[j] = (unsigned short)bd;
        msz++;
    }
    if (lane == 0) {
        #pragma unroll
        for (int j = 0; j < 8; j++) g_mem[i][j] = memb[j];
        g_msz[i] = msz;
        unsigned long long hi = 0, lo = 0;
        #pragma unroll
        for (int j = 0; j < 7; j++) {
            unsigned long long k = (j < msz) ? (unsigned long long)(8191u - memb[j]) : 0ull;
            if (j < 4) hi |= k << (48 - 16 * j);
            else       lo |= k << (48 - 16 * (j - 4));
        }
        g_khi[i] = hi; g_klo[i] = lo;   // lo bits [0:16) are free
    }
}

// single-block bitonic sort of 4096 128-bit keys (idx packed in lo[0:16)),
// fused with adjacent-dedup + compaction.
__global__ void k_sort_dedup() {   // <<<1,1024, 65536>>>
    extern __shared__ unsigned long long sk[];   // [2*4096]: hi, lo|idx
    __shared__ int sh[1024];
    int t = threadIdx.x;
    for (int r = t; r < N_NODES; r += 1024) {
        sk[2 * r] = g_khi[r];
        sk[2 * r + 1] = g_klo[r] | (unsigned long long)r;
    }
    __syncthreads();
    for (int k = 2; k <= N_NODES; k <<= 1) {
        for (int j = k >> 1; j > 0; j >>= 1) {
            for (int r = t; r < N_NODES; r += 1024) {
                int x = r ^ j;
                if (x > r) {
                    unsigned long long ah = sk[2 * r], al = sk[2 * r + 1];
                    unsigned long long bh = sk[2 * x], bl = sk[2 * x + 1];
                    bool agtb = (ah > bh) || (ah == bh && al > bl);
                    bool up = ((r & k) == 0);
                    if (agtb == up) {
                        sk[2 * r] = bh; sk[2 * r + 1] = bl;
                        sk[2 * x] = ah; sk[2 * x + 1] = al;
                    }
                }
            }
            __syncthreads();
        }
    }
    // dedup on (hi, lo & ~0xFFFF)
    int fl[4], loc[4];
    int s = 0;
    #pragma unroll
    for (int q = 0; q < 4; q++) {
        int r = t * 4 + q;
        int f;
        if (r == 0) f = 1;
        else {
            unsigned long long ph = sk[2 * (r - 1)], pl = sk[2 * (r - 1) + 1] & ~0xFFFFull;
            unsigned long long ch = sk[2 * r],       cl = sk[2 * r + 1] & ~0xFFFFull;
            f = (ph != ch) || (pl != cl);
        }
        fl[q] = f; loc[q] = s; s += f;
    }
    sh[t] = s; __syncthreads();
    for (int off = 1; off < 1024; off <<= 1) {
        int a = (t >= off) ? sh[t - off] : 0;
        __syncthreads();
        sh[t] += a;
        __syncthreads();
    }
    int pre = t ? sh[t - 1] : 0;
    #pragma unroll
    for (int q = 0; q < 4; q++) {
        int r = t * 4 + q;
        if (fl[q]) {
            int pos = pre + loc[q];
            int src = (int)(sk[2 * r + 1] & 0xFFFFull);
            #pragma unroll
            for (int j = 0; j < 8; j++) g_uniq[pos][j] = g_mem[src][j];
            g_usz[pos] = g_msz[src];
        }
    }
    if (t == 1023) g_U = sh[1023];
}

__global__ void k_n2u_cnt() {
    int u = blockIdx.x * blockDim.x + threadIdx.x;
    if (u >= g_U) return;
    int sz = g_usz[u];
    for (int mi = 0; mi < sz; mi++) atomicAdd(&g_n2ucnt[g_uniq[u][mi]], 1);
}

__global__ void k_n2u_fill() {
    int u = blockIdx.x * blockDim.x + threadIdx.x;
    if (u >= g_U) return;
    int sz = g_usz[u];
    for (int mi = 0; mi < sz; mi++) {
        int m = g_uniq[u][mi];
        int slot = g_n2uptr[m] + atomicAdd(&g_n2ufill[m], 1);
        g_n2ulist[slot] = u;
    }
}

// 256-thread persistent greedy max-cover with incremental uncovered-counts
__global__ void k_greedy() {   // <<<1,256>>>
    __shared__ int s_cnt[N_NODES];
    __shared__ unsigned s_cov[128];
    __shared__ int s_part[8];
    __shared__ int s_stop, s_nNew;
    __shared__ unsigned short s_newm[8];
    int t = threadIdx.x;
    int U = g_U;
    for (int c = t; c < N_NODES; c += 256) s_cnt[c] = (c < U) ? g_usz[c] : 0;
    for (int w = t; w < 128; w += 256) s_cov[w] = 0u;
    if (t == 0) s_stop = 0;
    __syncthreads();
    int wid = t >> 5, lane = t & 31;
    int covTot = 0, K = 0;                 // live in thread0 only
    while (true) {
        int key = 0;
        #pragma unroll
        for (int q = 0; q < 16; q++) {
            int c = t + 256 * q;
            int cc = s_cnt[c];
            int k2 = (cc << 12) | (4095 - c);
            if (cc > 0 && k2 > key) key = k2;
        }
        #pragma unroll
        for (int o = 16; o; o >>= 1) key = max(key, __shfl_down_sync(0xffffffffu, key, o));
        if (lane == 0) s_part[wid] = key;
        __syncthreads();
        if (t == 0) {
            int best = s_part[0];
            #pragma unroll
            for (int w = 1; w < 8; w++) best = max(best, s_part[w]);
            if (best == 0) { s_stop = 1; s_nNew = 0; }
            else {
                int c = 4095 - (best & 4095);
                g_sel[K] = c; K++;
                covTot += (best >> 12);
                int nn = 0, sz = g_usz[c];
                for (int mi = 0; mi < sz; mi++) {
                    unsigned short m = g_uniq[c][mi];
                    unsigned wv = s_cov[m >> 5];
                    if (!((wv >> (m & 31)) & 1u)) {
                        s_cov[m >> 5] = wv | (1u << (m & 31));
                        s_newm[nn++] = m;
                    }
                }
                s_nNew = nn;
                s_stop = (covTot >= N_NODES);
            }
        }
        __syncthreads();
        if (s_stop) break;
        if (wid < s_nNew) {
            int m = s_newm[wid];
            int b = g_n2uptr[m], e = g_n2uptr[m + 1];
            for (int p = b + lane; p < e; p += 32) atomicSub(&s_cnt[g_n2ulist[p]], 1);
        }
        __syncthreads();
    }
    if (t == 0) g_K = K;
}

__global__ void k_c2_cnt() {
    int k = blockIdx.x * blockDim.x + threadIdx.x;
    if (k >= g_K) return;
    int c = g_sel[k];
    int sz = g_usz[c];
    for (int mi = 0; mi < sz; mi++) atomicAdd(&g_c2cnt[g_uniq[c][mi]], 1);
}

__global__ void k_c2_fill() {
    int k = blockIdx.x * blockDim.x + threadIdx.x;
    if (k >= g_K) return;
    int c = g_sel[k];
    int sz = g_usz[c];
    for (int mi = 0; mi < sz; mi++) {
        int m = g_uniq[c][mi];
        int slot = g_c2ptr[m] + atomicAdd(&g_c2fill[m], 1);
        g_c2list[slot] = k;
    }
}

__global__ void k_clearB() {
    int tot = g_K * N_NODES;
    int stride = gridDim.x * blockDim.x;
    for (int i = blockIdx.x * blockDim.x + threadIdx.x; i < tot; i += stride)
        g_B[i] = 0;
}

__global__ void k_markB(const int* __restrict__ ei) {
    int e = blockIdx.x * 256 + threadIdx.x;
    int u = ei[e], v = ei[N_EDGES + e];
    int a0 = g_c2ptr[u], a1 = g_c2ptr[u + 1];
    int b0 = g_c2ptr[v], b1 = g_c2ptr[v + 1];
    for (int p = a0; p < a1; p++) {
        size_t base = (size_t)g_c2list[p] * N_NODES;
        for (int q = b0; q < b1; q++) g_B[base + g_c2list[q]] = 1;
    }
}

// warp-per-row popcount of adjacency rows
__global__ void k_rowcnt() {   // <<<512,256>>>
    int gw = (blockIdx.x * blockDim.x + threadIdx.x) >> 5;
    int lane = threadIdx.x & 31;
    if (gw >= N_NODES) return;
    int K = g_K;
    if (gw >= K) { if (lane == 0) g_rn[gw] = 0; return; }
    const unsigned* row = (const unsigned*)(g_B + (size_t)gw * N_NODES);
    int c = 0;
    #pragma unroll 4
    for (int j = lane; j < N_NODES / 4; j += 32) c += __popc(row[j]);
    #pragma unroll
    for (int o = 16; o; o >>= 1) c += __shfl_down_sync(0xffffffffu, c, o);
    if (lane == 0) g_rn[gw] = c - (int)g_B[(size_t)gw * N_NODES + gw];
}

// warp-per-row ballot compaction into the edge list
__global__ void k_write_edges(float* __restrict__ out) {   // <<<512,256>>>
    int gw = (blockIdx.x * blockDim.x + threadIdx.x) >> 5;
    int lane = threadIdx.x & 31;
    if (gw >= N_NODES) return;
    int K = g_K;
    if (gw >= K) return;
    int nnz = g_roff[K];
    const unsigned char* row = g_B + (size_t)gw * N_NODES;
    int p = g_roff[gw];
    for (int base = 0; base < K; base += 32) {
        int j = base + lane;
        bool v = (j < K) && (j != gw) && (row[j] != 0);
        unsigned m = __ballot_sync(0xffffffffu, v);
        if (v) {
            int off = __popc(m & ((1u << lane) - 1));
            out[p + off] = (float)gw;
            out[nnz + p + off] = (float)j;
        }
        p += __popc(m);
    }
}

__global__ void k_xnew(const float* __restrict__ x, float* __restrict__ out) {
    int k = blockIdx.x;
    if (k >= g_K) return;
    int c = g_sel[k];
    int sz = g_usz[c];
    int d = threadIdx.x;
    float acc = 0.f;
    for (int mi = 0; mi < sz; mi++) {
        int m = g_uniq[c][mi];
        acc += g_avg[m] * x[(size_t)m * D_FEAT + d];
    }
    int off = 2 * g_roff[g_K];
    out[off + k * D_FEAT + d] = acc;
}

__global__ void k_zeroSM(float* __restrict__ out) {
    int K = g_K;
    int nnz = g_roff[K];
    int offS = 2 * nnz + K * D_FEAT;
    int tot = 2 * K * N_NODES;
    int stride = gridDim.x * blockDim.x;
    for (int i = blockIdx.x * blockDim.x + threadIdx.x; i < tot; i += stride)
        out[offS + i] = 0.f;
}

__global__ void k_scatterSM(float* __restrict__ out) {
    int t = blockIdx.x * blockDim.x + threadIdx.x;
    int K = g_K;
    if (t >= K) return;
    int nnz = g_roff[K];
    int offS = 2 * nnz + K * D_FEAT;
    int offM = offS + K * N_NODES;
    int c = g_sel[t];
    int sz = g_usz[c];
    for (int mi = 0; mi < sz; mi++) {
        int m = g_uniq[c][mi];
        out[offS + t * N_NODES + m] = 1.0f;
        out[offM + t * N_NODES + m] = g_avg[m];
    }
}

__global__ void k_copyEI(const int* __restrict__ ei, float* __restrict__ out) {
    int i = blockIdx.x * blockDim.x + threadIdx.x;
    if (i >= 2 * N_EDGES) return;
    int K = g_K;
    int off = 2 * g_roff[K] + K * D_FEAT + 2 * K * N_NODES;
    out[off + i] = (float)ei[i];
}

// ------------------------- launch -------------------------
extern "C" void kernel_launch(void* const* d_in, const int* in_sizes, int n_in,
                              void* d_out, int out_size) {
    const float* x  = (const float*)d_in[0];
    const int*   ei = (const int*)d_in[1];
    float*       out = (float*)d_out;
    cudaStream_t st = cudaStreamPerThread;

    cudaFuncSetAttribute(k_sort_dedup, cudaFuncAttributeMaxDynamicSharedMemorySize, 65536);

    k_init       <<<16, 256, 0, st>>>();
    k_dist       <<<N_EDGES / 8, 256, 0, st>>>(x, ei);
    k_scan4096   <<<1, 1024, 0, st>>>(0);            // deg -> rowptr
    k_norm_fill  <<<N_EDGES / 256, 256, 0, st>>>(ei);
    k_avg        <<<16, 256, 0, st>>>();
    k_grow       <<<512, 256, 0, st>>>();
    k_sort_dedup <<<1, 1024, 65536, st>>>();
    k_n2u_cnt    <<<16, 256, 0, st>>>();
    k_scan4096   <<<1, 1024, 0, st>>>(1);            // n2ucnt -> n2uptr
    k_n2u_fill   <<<16, 256, 0, st>>>();
    k_greedy     <<<1, 256, 0, st>>>();
    k_c2_cnt     <<<16, 256, 0, st>>>();
    k_scan4096   <<<1, 1024, 0, st>>>(2);            // c2cnt -> c2ptr
    k_c2_fill    <<<16, 256, 0, st>>>();
    k_clearB     <<<2048, 256, 0, st>>>();
    k_markB      <<<N_EDGES / 256, 256, 0, st>>>(ei);
    k_rowcnt     <<<512, 256, 0, st>>>();
    k_scan4096   <<<1, 1024, 0, st>>>(3);            // rn -> roff
    k_write_edges<<<512, 256, 0, st>>>(out);
    k_xnew       <<<N_NODES, 256, 0, st>>>(x, out);
    k_zeroSM     <<<2048, 256, 0, st>>>(out);
    k_scatterSM  <<<16, 256, 0, st>>>(out);
    k_copyEI     <<<512, 256, 0, st>>>(ei, out);
}

// round 3
// speedup vs baseline: 2.4509x; 1.3380x over previous
#include <cuda_runtime.h>
#include <cstdint>

#define N_NODES 4096
#define D_FEAT  256
#define N_EDGES 65536

// ------------------------- static device scratch -------------------------
static __device__ float g_sraw[N_EDGES];
static __device__ unsigned g_minb, g_maxb;
static __device__ int   g_deg[N_NODES];
static __device__ int   g_rowptr[N_NODES + 1];
static __device__ int   g_fill[N_NODES];
static __device__ unsigned long long g_csr_key[N_EDGES];   // (score_bits<<32)|eid
static __device__ int   g_csr_dst[N_EDGES];
static __device__ float g_tot[N_NODES];
static __device__ int   g_cntN[N_NODES];
static __device__ float g_avg[N_NODES];
static __device__ __align__(16) unsigned short g_mem[N_NODES][8];
static __device__ int   g_msz[N_NODES];
static __device__ unsigned long long g_khi[N_NODES], g_klo[N_NODES];
static __device__ __align__(16) unsigned short g_uniq[N_NODES][8];
static __device__ int   g_usz[N_NODES];
static __device__ int   g_U;
static __device__ int   g_n2ucnt[N_NODES], g_n2uptr[N_NODES + 1], g_n2ufill[N_NODES];
static __device__ int   g_n2ulist[N_NODES * 8];
static __device__ int   g_sel[N_NODES];
static __device__ int   g_K;
static __device__ int   g_c2cnt[N_NODES], g_c2ptr[N_NODES + 1], g_c2fill[N_NODES];
static __device__ int   g_c2list[N_NODES * 8];
static __device__ unsigned char g_B[(size_t)N_NODES * N_NODES];   // cluster adj bitmap
static __device__ int   g_rn[N_NODES], g_roff[N_NODES + 1];

// ------------------------- kernels -------------------------

__global__ void k_init() {
    int i = blockIdx.x * blockDim.x + threadIdx.x;
    if (i < N_NODES) {
        g_deg[i] = 0; g_fill[i] = 0;
        g_tot[i] = 0.f; g_cntN[i] = 0;
        g_n2ucnt[i] = 0; g_n2ufill[i] = 0;
        g_c2cnt[i] = 0; g_c2fill[i] = 0;
    }
    if (i == 0) { g_minb = 0x7f800000u; g_maxb = 0u; }
}

// one warp per edge: distance, degree count, block-reduced global min/max
__global__ void k_dist(const float* __restrict__ x, const int* __restrict__ ei) {
    int warp = threadIdx.x >> 5, lane = threadIdx.x & 31;
    int e = blockIdx.x * 8 + warp;
    __shared__ float smin[8], smax[8];
    float sval = __int_as_float(0x7f800000);
    {
        int u = ei[e], v = ei[N_EDGES + e];
        const float* xu = x + (size_t)u * D_FEAT;
        const float* xv = x + (size_t)v * D_FEAT;
        double acc = 0.0;
        #pragma unroll
        for (int i = 0; i < 8; i++) {
            float a = xu[lane + 32 * i], b = xv[lane + 32 * i];
            double d = (double)a - (double)b;
            acc += d * d;
        }
        #pragma unroll
        for (int o = 16; o; o >>= 1) acc += __shfl_down_sync(0xffffffffu, acc, o);
        if (lane == 0) {
            float sf = (float)acc;
            float s = sqrtf(sf + 1e-12f);
            g_sraw[e] = s;
            atomicAdd(&g_deg[u], 1);
            sval = s;
        }
    }
    if (lane == 0) { smin[warp] = sval; smax[warp] = sval; }
    __syncthreads();
    if (threadIdx.x == 0) {
        float mn = smin[0], mx = smax[0];
        #pragma unroll
        for (int i = 1; i < 8; i++) { mn = fminf(mn, smin[i]); mx = fmaxf(mx, smax[i]); }
        atomicMin(&g_minb, __float_as_uint(mn));
        atomicMax(&g_maxb, __float_as_uint(mx));
    }
}

// exclusive scan of a fixed 4096-int array selected by `which`
__global__ void k_scan4096(int which) {
    const int* in; int* out;
    switch (which) {
        case 0:  in = g_deg;    out = g_rowptr;  break;
        case 1:  in = g_n2ucnt; out = g_n2uptr;  break;
        case 2:  in = g_c2cnt;  out = g_c2ptr;   break;
        default: in = g_rn;     out = g_roff;    break;
    }
    __shared__ int sh[1024];
    int t = threadIdx.x;
    int v0 = in[t * 4 + 0], v1 = in[t * 4 + 1], v2 = in[t * 4 + 2], v3 = in[t * 4 + 3];
    int s = v0 + v1 + v2 + v3;
    sh[t] = s; __syncthreads();
    for (int off = 1; off < 1024; off <<= 1) {
        int a = (t >= off) ? sh[t - off] : 0;
        __syncthreads();
        sh[t] += a;
        __syncthreads();
    }
    int pre = t ? sh[t - 1] : 0;
    out[t * 4 + 0] = pre;
    out[t * 4 + 1] = pre + v0;
    out[t * 4 + 2] = pre + v0 + v1;
    out[t * 4 + 3] = pre + v0 + v1 + v2;
    if (t == 1023) out[4096] = sh[1023];
}

__global__ void k_norm_fill(const int* __restrict__ ei) {
    int e = blockIdx.x * 256 + threadIdx.x;
    float mn = __uint_as_float(g_minb), mx = __uint_as_float(g_maxb);
    float s = (g_sraw[e] - mn) / (mx - mn) + 0.5f;
    int u = ei[e], v = ei[N_EDGES + e];
    atomicAdd(&g_tot[u], s); atomicAdd(&g_tot[v], s);
    atomicAdd(&g_cntN[u], 1); atomicAdd(&g_cntN[v], 1);
    int slot = g_rowptr[u] + atomicAdd(&g_fill[u], 1);
    g_csr_key[slot] = ((unsigned long long)__float_as_uint(s) << 32) | (unsigned)e;
    g_csr_dst[slot] = v;
}

__global__ void k_avg() {
    int i = blockIdx.x * blockDim.x + threadIdx.x;
    if (i < N_NODES) g_avg[i] = g_tot[i] / (float)g_cntN[i];
}

// warp-per-seed Prim-style growth; members register-resident via predicated
// unrolled loops; warp argmin over 64-bit (score,eid) keys.
__global__ void k_grow() {   // <<<512,256>>>
    int wid = threadIdx.x >> 5, lane = threadIdx.x & 31;
    int i = blockIdx.x * 8 + wid;
    unsigned short memb[8];
    #pragma unroll
    for (int j = 0; j < 8; j++) memb[j] = 0xFFFF;
    #pragma unroll
    for (int j = 0; j < 8; j++) if (j == 0) memb[j] = (unsigned short)i;
    int msz = 1; float tot = 0.f;
    while (tot < 3.0f && msz < 8) {
        unsigned long long bk = ~0ull; int bd = -1;
        #pragma unroll
        for (int mi = 0; mi < 7; mi++) {
            if (mi >= msz) break;
            int u = -1;
            #pragma unroll
            for (int j = 0; j < 7; j++) if (j == mi) u = memb[j];
            int p0 = g_rowptr[u], p1 = g_rowptr[u + 1];
            for (int p = p0 + lane; p < p1; p += 32) {
                int d = g_csr_dst[p];
                bool in = false;
                #pragma unroll
                for (int j = 0; j < 7; j++) in |= (j < msz) && (memb[j] == (unsigned short)d);
                if (in) continue;
                unsigned long long key = g_csr_key[p];
                if (key < bk) { bk = key; bd = d; }
            }
        }
        #pragma unroll
        for (int o = 16; o; o >>= 1) {
            unsigned long long ok = __shfl_down_sync(0xffffffffu, bk, o);
            int od = __shfl_down_sync(0xffffffffu, bd, o);
            if (ok < bk) { bk = ok; bd = od; }
        }
        bk = __shfl_sync(0xffffffffu, bk, 0);
        bd = __shfl_sync(0xffffffffu, bd, 0);
        if (bd < 0) break;
        tot += __uint_as_float((unsigned)(bk >> 32));
        // sorted insert (replicated in all lanes, register-resident)
        int pos = 0;
        #pragma unroll
        for (int j = 0; j < 7; j++) pos += (j < msz && memb[j] < (unsigned short)bd);
        #pragma unroll
        for (int j = 6; j >= 0; j--) if (j >= pos && j < msz) memb[j + 1] = memb[j];
        #pragma unroll
        for (int j = 0; j < 8; j++) if (j == pos) memb[j] = (unsigned short)bd;
        msz++;
    }
    if (lane == 0) {
        #pragma unroll
        for (int j = 0; j < 8; j++) g_mem[i][j] = memb[j];
        g_msz[i] = msz;
        unsigned long long hi = 0, lo = 0;
        #pragma unroll
        for (int j = 0; j < 7; j++) {
            unsigned long long k = (j < msz) ? (unsigned long long)(8191u - memb[j]) : 0ull;
            if (j < 4) hi |= k << (48 - 16 * j);
            else       lo |= k << (48 - 16 * (j - 4));
        }
        g_khi[i] = hi; g_klo[i] = lo;   // lo bits [0:16) are free
    }
}

// single-block bitonic sort of 4096 128-bit keys (idx packed in lo[0:16)),
// fused with adjacent-dedup + compaction.
__global__ void k_sort_dedup() {   // <<<1,1024, 65536>>>
    extern __shared__ unsigned long long sk[];   // [2*4096]: hi, lo|idx
    __shared__ int sh[1024];
    int t = threadIdx.x;
    for (int r = t; r < N_NODES; r += 1024) {
        sk[2 * r] = g_khi[r];
        sk[2 * r + 1] = g_klo[r] | (unsigned long long)r;
    }
    __syncthreads();
    for (int k = 2; k <= N_NODES; k <<= 1) {
        for (int j = k >> 1; j > 0; j >>= 1) {
            for (int r = t; r < N_NODES; r += 1024) {
                int x = r ^ j;
                if (x > r) {
                    unsigned long long ah = sk[2 * r], al = sk[2 * r + 1];
                    unsigned long long bh = sk[2 * x], bl = sk[2 * x + 1];
                    bool agtb = (ah > bh) || (ah == bh && al > bl);
                    bool up = ((r & k) == 0);
                    if (agtb == up) {
                        sk[2 * r] = bh; sk[2 * r + 1] = bl;
                        sk[2 * x] = ah; sk[2 * x + 1] = al;
                    }
                }
            }
            __syncthreads();
        }
    }
    // dedup on (hi, lo & ~0xFFFF)
    int fl[4], loc[4];
    int s = 0;
    #pragma unroll
    for (int q = 0; q < 4; q++) {
        int r = t * 4 + q;
        int f;
        if (r == 0) f = 1;
        else {
            unsigned long long ph = sk[2 * (r - 1)], pl = sk[2 * (r - 1) + 1] & ~0xFFFFull;
            unsigned long long ch = sk[2 * r],       cl = sk[2 * r + 1] & ~0xFFFFull;
            f = (ph != ch) || (pl != cl);
        }
        fl[q] = f; loc[q] = s; s += f;
    }
    sh[t] = s; __syncthreads();
    for (int off = 1; off < 1024; off <<= 1) {
        int a = (t >= off) ? sh[t - off] : 0;
        __syncthreads();
        sh[t] += a;
        __syncthreads();
    }
    int pre = t ? sh[t - 1] : 0;
    #pragma unroll
    for (int q = 0; q < 4; q++) {
        int r = t * 4 + q;
        if (fl[q]) {
            int pos = pre + loc[q];
            int src = (int)(sk[2 * r + 1] & 0xFFFFull);
            #pragma unroll
            for (int j = 0; j < 8; j++) g_uniq[pos][j] = g_mem[src][j];
            g_usz[pos] = g_msz[src];
        }
    }
    if (t == 1023) g_U = sh[1023];
}

__global__ void k_n2u_cnt() {
    int u = blockIdx.x * blockDim.x + threadIdx.x;
    if (u >= g_U) return;
    int sz = g_usz[u];
    for (int mi = 0; mi < sz; mi++) atomicAdd(&g_n2ucnt[g_uniq[u][mi]], 1);
}

__global__ void k_n2u_fill() {
    int u = blockIdx.x * blockDim.x + threadIdx.x;
    if (u >= g_U) return;
    int sz = g_usz[u];
    for (int mi = 0; mi < sz; mi++) {
        int m = g_uniq[u][mi];
        int slot = g_n2uptr[m] + atomicAdd(&g_n2ufill[m], 1);
        g_n2ulist[slot] = u;
    }
}

// ---------------- single-warp bucketed greedy max-cover ----------------
// All state in SMEM. counts <= 7 => 8 count-buckets as 4096-bit bitmaps.
// Selection = find-first-set in highest nonempty bucket (bound monotone).
#define G_OFF_CNT   0         // int[4096]
#define G_OFF_PTR   16384     // int[4097] (padded to 16400)
#define G_OFF_UQ    32784     // u16[4096*8]
#define G_OFF_SZ    98320     // u8[4096]
#define G_OFF_LS    102416    // u16[32768]
#define G_OFF_BKT   167952    // u32[8*128]
#define G_OFF_COV   172048    // u32[128]
#define G_OFF_NM    172560    // int[8]
#define G_OFF_BEG   172592    // int[8]
#define G_OFF_OFF   172624    // int[8]
#define G_SMEM_TOT  172672

__global__ void k_greedy() {   // <<<1,256, G_SMEM_TOT>>>
    extern __shared__ unsigned char sg[];
    int* s_cnt           = (int*)(sg + G_OFF_CNT);
    int* s_ptr           = (int*)(sg + G_OFF_PTR);
    unsigned short* s_uq = (unsigned short*)(sg + G_OFF_UQ);
    unsigned char* s_sz  = (unsigned char*)(sg + G_OFF_SZ);
    unsigned short* s_ls = (unsigned short*)(sg + G_OFF_LS);
    unsigned* s_bkt      = (unsigned*)(sg + G_OFF_BKT);
    unsigned* s_cov      = (unsigned*)(sg + G_OFF_COV);
    int* s_nm            = (int*)(sg + G_OFF_NM);
    int* s_beg           = (int*)(sg + G_OFF_BEG);
    int* s_off           = (int*)(sg + G_OFF_OFF);

    int t = threadIdx.x;
    int U = g_U;
    int T = g_n2uptr[N_NODES];

    for (int i = t; i < 8 * 128; i += 256) s_bkt[i] = 0;
    for (int i = t; i < 128; i += 256) s_cov[i] = 0;
    __syncthreads();
    for (int c = t; c < N_NODES; c += 256) {
        int cc = (c < U) ? g_usz[c] : 0;
        s_cnt[c] = cc;
        s_sz[c] = (unsigned char)cc;
        ((uint4*)s_uq)[c] = ((const uint4*)g_uniq)[c];
        if (cc > 0) atomicOr(&s_bkt[cc * 128 + (c >> 5)], 1u << (c & 31));
    }
    for (int i = t; i <= N_NODES; i += 256) s_ptr[i] = g_n2uptr[i];
    for (int i = t; i < T; i += 256) s_ls[i] = (unsigned short)g_n2ulist[i];
    __syncthreads();
    if (t >= 32) return;

    int lane = t;
    int covered = 0, K = 0, maxb = 7;
    while (covered < N_NODES) {
        // ---- selection: first-set in highest nonempty bucket ----
        int c = -1;
        while (maxb >= 1) {
            uint4 v4 = ((const uint4*)(s_bkt + maxb * 128))[lane];
            int local = 0x7fffffff;
            if (v4.x) local = min(local, ((lane * 4 + 0) << 5) + __ffs(v4.x) - 1);
            if (v4.y) local = min(local, ((lane * 4 + 1) << 5) + __ffs(v4.y) - 1);
            if (v4.z) local = min(local, ((lane * 4 + 2) << 5) + __ffs(v4.z) - 1);
            if (v4.w) local = min(local, ((lane * 4 + 3) << 5) + __ffs(v4.w) - 1);
            local = __reduce_min_sync(0xffffffffu, local);
            if (local != 0x7fffffff) { c = local; break; }
            maxb--;
        }
        if (c < 0) break;
        if (lane == 0) g_sel[K] = c;
        K++;
        // ---- mark newly covered members (sz <= 7, lane-parallel) ----
        int sz = s_sz[c];
        int m = (lane < sz) ? (int)s_uq[c * 8 + lane] : -1;
        bool isnew = false;
        if (m >= 0) {
            unsigned w = s_cov[m >> 5];
            isnew = !((w >> (m & 31)) & 1u);
        }
        if (isnew) atomicOr(&s_cov[m >> 5], 1u << (m & 31));
        unsigned nb = __ballot_sync(0xffffffffu, isnew);
        int newcnt = __popc(nb);
        covered += newcnt;
        if (isnew) s_nm[__popc(nb & ((1u << lane) - 1))] = m;
        __syncwarp();
        // ---- flatten decrement lists of the new nodes ----
        int len = 0, beg = 0;
        if (lane < newcnt) { int mm = s_nm[lane]; beg = s_ptr[mm]; len = s_ptr[mm + 1] - beg; }
        int pre = len;
        #pragma unroll
        for (int o = 1; o < 8; o <<= 1) {
            int v = __shfl_up_sync(0xffffffffu, pre, o);
            if (lane >= o) pre += v;
        }
        int tot = __shfl_sync(0xffffffffu, pre, 7);
        if (lane < newcnt) { s_beg[lane] = beg; s_off[lane] = pre - len; }
        __syncwarp();
        // ---- decrement counts ----
        for (int p = lane; p < tot; p += 32) {
            int k = 0;
            while (k + 1 < newcnt && p >= s_off[k + 1]) k++;
            int c2 = (int)s_ls[s_beg[k] + (p - s_off[k])];
            atomicSub(&s_cnt[c2], 1);
        }
        __syncwarp();
        // ---- repair buckets of affected clusters (idempotent) ----
        for (int p = lane; p < tot; p += 32) {
            int k = 0;
            while (k + 1 < newcnt && p >= s_off[k + 1]) k++;
            int c2 = (int)s_ls[s_beg[k] + (p - s_off[k])];
            int cc = s_cnt[c2];
            unsigned w = c2 >> 5, bit = 1u << (c2 & 31);
            #pragma unroll
            for (int b = 1; b < 8; b++)
                if (b != cc) atomicAnd(&s_bkt[b * 128 + w], ~bit);
            if (cc > 0) atomicOr(&s_bkt[cc * 128 + w], bit);
        }
        __syncwarp();
    }
    if (lane == 0) g_K = K;
}

__global__ void k_c2_cnt() {
    int k = blockIdx.x * blockDim.x + threadIdx.x;
    if (k >= g_K) return;
    int c = g_sel[k];
    int sz = g_usz[c];
    for (int mi = 0; mi < sz; mi++) atomicAdd(&g_c2cnt[g_uniq[c][mi]], 1);
}

__global__ void k_c2_fill() {
    int k = blockIdx.x * blockDim.x + threadIdx.x;
    if (k >= g_K) return;
    int c = g_sel[k];
    int sz = g_usz[c];
    for (int mi = 0; mi < sz; mi++) {
        int m = g_uniq[c][mi];
        int slot = g_c2ptr[m] + atomicAdd(&g_c2fill[m], 1);
        g_c2list[slot] = k;
    }
}

__global__ void k_clearB() {
    int tot = g_K * N_NODES;
    int stride = gridDim.x * blockDim.x;
    for (int i = blockIdx.x * blockDim.x + threadIdx.x; i < tot; i += stride)
        g_B[i] = 0;
}

__global__ void k_markB(const int* __restrict__ ei) {
    int e = blockIdx.x * 256 + threadIdx.x;
    int u = ei[e], v = ei[N_EDGES + e];
    int a0 = g_c2ptr[u], a1 = g_c2ptr[u + 1];
    int b0 = g_c2ptr[v], b1 = g_c2ptr[v + 1];
    for (int p = a0; p < a1; p++) {
        size_t base = (size_t)g_c2list[p] * N_NODES;
        for (int q = b0; q < b1; q++) g_B[base + g_c2list[q]] = 1;
    }
}

// warp-per-row popcount of adjacency rows
__global__ void k_rowcnt() {   // <<<512,256>>>
    int gw = (blockIdx.x * blockDim.x + threadIdx.x) >> 5;
    int lane = threadIdx.x & 31;
    if (gw >= N_NODES) return;
    int K = g_K;
    if (gw >= K) { if (lane == 0) g_rn[gw] = 0; return; }
    const unsigned* row = (const unsigned*)(g_B + (size_t)gw * N_NODES);
    int c = 0;
    #pragma unroll 4
    for (int j = lane; j < N_NODES / 4; j += 32) c += __popc(row[j]);
    #pragma unroll
    for (int o = 16; o; o >>= 1) c += __shfl_down_sync(0xffffffffu, c, o);
    if (lane == 0) g_rn[gw] = c - (int)g_B[(size_t)gw * N_NODES + gw];
}

// warp-per-row ballot compaction into the edge list
__global__ void k_write_edges(float* __restrict__ out) {   // <<<512,256>>>
    int gw = (blockIdx.x * blockDim.x + threadIdx.x) >> 5;
    int lane = threadIdx.x & 31;
    if (gw >= N_NODES) return;
    int K = g_K;
    if (gw >= K) return;
    int nnz = g_roff[K];
    const unsigned char* row = g_B + (size_t)gw * N_NODES;
    int p = g_roff[gw];
    for (int base = 0; base < K; base += 32) {
        int j = base + lane;
        bool v = (j < K) && (j != gw) && (row[j] != 0);
        unsigned m = __ballot_sync(0xffffffffu, v);
        if (v) {
            int off = __popc(m & ((1u << lane) - 1));
            out[p + off] = (float)gw;
            out[nnz + p + off] = (float)j;
        }
        p += __popc(m);
    }
}

__global__ void k_xnew(const float* __restrict__ x, float* __restrict__ out) {
    int k = blockIdx.x;
    if (k >= g_K) return;
    int c = g_sel[k];
    int sz = g_usz[c];
    int d = threadIdx.x;
    float acc = 0.f;
    for (int mi = 0; mi < sz; mi++) {
        int m = g_uniq[c][mi];
        acc += g_avg[m] * x[(size_t)m * D_FEAT + d];
    }
    int off = 2 * g_roff[g_K];
    out[off + k * D_FEAT + d] = acc;
}

__global__ void k_zeroSM(float* __restrict__ out) {
    int K = g_K;
    int nnz = g_roff[K];
    int offS = 2 * nnz + K * D_FEAT;
    int tot = 2 * K * N_NODES;
    int stride = gridDim.x * blockDim.x;
    for (int i = blockIdx.x * blockDim.x + threadIdx.x; i < tot; i += stride)
        out[offS + i] = 0.f;
}

__global__ void k_scatterSM(float* __restrict__ out) {
    int t = blockIdx.x * blockDim.x + threadIdx.x;
    int K = g_K;
    if (t >= K) return;
    int nnz = g_roff[K];
    int offS = 2 * nnz + K * D_FEAT;
    int offM = offS + K * N_NODES;
    int c = g_sel[t];
    int sz = g_usz[c];
    for (int mi = 0; mi < sz; mi++) {
        int m = g_uniq[c][mi];
        out[offS + t * N_NODES + m] = 1.0f;
        out[offM + t * N_NODES + m] = g_avg[m];
    }
}

__global__ void k_copyEI(const int* __restrict__ ei, float* __restrict__ out) {
    int i = blockIdx.x * blockDim.x + threadIdx.x;
    if (i >= 2 * N_EDGES) return;
    int K = g_K;
    int off = 2 * g_roff[K] + K * D_FEAT + 2 * K * N_NODES;
    out[off + i] = (float)ei[i];
}

// ------------------------- launch -------------------------
extern "C" void kernel_launch(void* const* d_in, const int* in_sizes, int n_in,
                              void* d_out, int out_size) {
    const float* x  = (const float*)d_in[0];
    const int*   ei = (const int*)d_in[1];
    float*       out = (float*)d_out;
    cudaStream_t st = cudaStreamPerThread;

    cudaFuncSetAttribute(k_sort_dedup, cudaFuncAttributeMaxDynamicSharedMemorySize, 65536);
    cudaFuncSetAttribute(k_greedy, cudaFuncAttributeMaxDynamicSharedMemorySize, G_SMEM_TOT);

    k_init       <<<16, 256, 0, st>>>();
    k_dist       <<<N_EDGES / 8, 256, 0, st>>>(x, ei);
    k_scan4096   <<<1, 1024, 0, st>>>(0);            // deg -> rowptr
    k_norm_fill  <<<N_EDGES / 256, 256, 0, st>>>(ei);
    k_avg        <<<16, 256, 0, st>>>();
    k_grow       <<<512, 256, 0, st>>>();
    k_sort_dedup <<<1, 1024, 65536, st>>>();
    k_n2u_cnt    <<<16, 256, 0, st>>>();
    k_scan4096   <<<1, 1024, 0, st>>>(1);            // n2ucnt -> n2uptr
    k_n2u_fill   <<<16, 256, 0, st>>>();
    k_greedy     <<<1, 256, G_SMEM_TOT, st>>>();
    k_c2_cnt     <<<16, 256, 0, st>>>();
    k_scan4096   <<<1, 1024, 0, st>>>(2);            // c2cnt -> c2ptr
    k_c2_fill    <<<16, 256, 0, st>>>();
    k_clearB     <<<2048, 256, 0, st>>>();
    k_markB      <<<N_EDGES / 256, 256, 0, st>>>(ei);
    k_rowcnt     <<<512, 256, 0, st>>>();
    k_scan4096   <<<1, 1024, 0, st>>>(3);            // rn -> roff
    k_write_edges<<<512, 256, 0, st>>>(out);
    k_xnew       <<<N_NODES, 256, 0, st>>>(x, out);
    k_zeroSM     <<<2048, 256, 0, st>>>(out);
    k_scatterSM  <<<16, 256, 0, st>>>(out);
    k_copyEI     <<<512, 256, 0, st>>>(ei, out);
}

// round 6
// speedup vs baseline: 2.5994x; 1.0606x over previous
#include <cuda_runtime.h>
#include <cstdint>

#define N_NODES 4096
#define D_FEAT  256
#define N_EDGES 65536

// ------------------------- static device scratch -------------------------
static __device__ float g_sraw[N_EDGES];
static __device__ unsigned g_minb, g_maxb;
static __device__ int   g_deg[N_NODES];
static __device__ int   g_rowptr[N_NODES + 1];
static __device__ int   g_fill[N_NODES];
static __device__ unsigned long long g_csr_key[N_EDGES];   // (score_bits<<32)|eid
static __device__ int   g_csr_dst[N_EDGES];
static __device__ float g_tot[N_NODES];
static __device__ int   g_cntN[N_NODES];
static __device__ float g_avg[N_NODES];
static __device__ __align__(16) unsigned short g_mem[N_NODES][8];
static __device__ int   g_msz[N_NODES];
static __device__ unsigned long long g_khi[N_NODES], g_klo[N_NODES];
static __device__ __align__(16) unsigned short g_uniq[N_NODES][8];
static __device__ int   g_usz[N_NODES];
static __device__ int   g_U;
static __device__ int   g_n2uptr[N_NODES + 1];
static __device__ int   g_n2ulist[N_NODES * 8];
static __device__ int   g_sel[N_NODES];
static __device__ int   g_K;
static __device__ int   g_c2ptr[N_NODES + 1];
static __device__ int   g_c2list[N_NODES * 8];
static __device__ unsigned char g_B[(size_t)N_NODES * N_NODES];   // cluster adj bitmap
static __device__ int   g_rn[N_NODES], g_roff[N_NODES + 1];

// ------------------------- kernels -------------------------

__global__ void k_init() {
    int i = blockIdx.x * blockDim.x + threadIdx.x;
    if (i < N_NODES) {
        g_deg[i] = 0; g_fill[i] = 0;
        g_tot[i] = 0.f; g_cntN[i] = 0;
    }
    if (i == 0) { g_minb = 0x7f800000u; g_maxb = 0u; }
}

// one warp per edge: distance, degree count, block-reduced global min/max
__global__ void k_dist(const float* __restrict__ x, const int* __restrict__ ei) {
    int warp = threadIdx.x >> 5, lane = threadIdx.x & 31;
    int e = blockIdx.x * 8 + warp;
    __shared__ float smin[8], smax[8];
    float sval = __int_as_float(0x7f800000);
    {
        int u = ei[e], v = ei[N_EDGES + e];
        const float* xu = x + (size_t)u * D_FEAT;
        const float* xv = x + (size_t)v * D_FEAT;
        double acc = 0.0;
        #pragma unroll
        for (int i = 0; i < 8; i++) {
            float a = xu[lane + 32 * i], b = xv[lane + 32 * i];
            double d = (double)a - (double)b;
            acc += d * d;
        }
        #pragma unroll
        for (int o = 16; o; o >>= 1) acc += __shfl_down_sync(0xffffffffu, acc, o);
        if (lane == 0) {
            float sf = (float)acc;
            float s = sqrtf(sf + 1e-12f);
            g_sraw[e] = s;
            atomicAdd(&g_deg[u], 1);
            sval = s;
        }
    }
    if (lane == 0) { smin[warp] = sval; smax[warp] = sval; }
    __syncthreads();
    if (threadIdx.x == 0) {
        float mn = smin[0], mx = smax[0];
        #pragma unroll
        for (int i = 1; i < 8; i++) { mn = fminf(mn, smin[i]); mx = fmaxf(mx, smax[i]); }
        atomicMin(&g_minb, __float_as_uint(mn));
        atomicMax(&g_maxb, __float_as_uint(mx));
    }
}

// exclusive scan of a fixed 4096-int array selected by `which`
__global__ void k_scan4096(int which) {
    const int* in; int* out;
    if (which == 0) { in = g_deg; out = g_rowptr; }
    else            { in = g_rn;  out = g_roff;   }
    __shared__ int sh[1024];
    int t = threadIdx.x;
    int v0 = in[t * 4 + 0], v1 = in[t * 4 + 1], v2 = in[t * 4 + 2], v3 = in[t * 4 + 3];
    int s = v0 + v1 + v2 + v3;
    sh[t] = s; __syncthreads();
    for (int off = 1; off < 1024; off <<= 1) {
        int a = (t >= off) ? sh[t - off] : 0;
        __syncthreads();
        sh[t] += a;
        __syncthreads();
    }
    int pre = t ? sh[t - 1] : 0;
    out[t * 4 + 0] = pre;
    out[t * 4 + 1] = pre + v0;
    out[t * 4 + 2] = pre + v0 + v1;
    out[t * 4 + 3] = pre + v0 + v1 + v2;
    if (t == 1023) out[4096] = sh[1023];
}

__global__ void k_norm_fill(const int* __restrict__ ei) {
    int e = blockIdx.x * 256 + threadIdx.x;
    float mn = __uint_as_float(g_minb), mx = __uint_as_float(g_maxb);
    float s = (g_sraw[e] - mn) / (mx - mn) + 0.5f;
    int u = ei[e], v = ei[N_EDGES + e];
    atomicAdd(&g_tot[u], s); atomicAdd(&g_tot[v], s);
    atomicAdd(&g_cntN[u], 1); atomicAdd(&g_cntN[v], 1);
    int slot = g_rowptr[u] + atomicAdd(&g_fill[u], 1);
    g_csr_key[slot] = ((unsigned long long)__float_as_uint(s) << 32) | (unsigned)e;
    g_csr_dst[slot] = v;
}

__global__ void k_avg() {
    int i = blockIdx.x * blockDim.x + threadIdx.x;
    if (i < N_NODES) g_avg[i] = g_tot[i] / (float)g_cntN[i];
}

// warp-per-seed Prim-style growth with per-row cached best candidates.
// A cached row-min only invalidates when its dst joins the cluster.
__global__ void __launch_bounds__(256) k_grow() {   // <<<512,256>>>
    int wid = threadIdx.x >> 5, lane = threadIdx.x & 31;
    int seed = blockIdx.x * 8 + wid;
    unsigned short joined[8];
    unsigned long long ck[8];
    int cd[8];
    #pragma unroll
    for (int j = 0; j < 8; j++) { joined[j] = 0xFFFF; ck[j] = ~0ull; cd[j] = -1; }
    joined[0] = (unsigned short)seed;
    int nj = 1; float tot = 0.f;

    // initial scan of seed row
    {
        unsigned long long bk = ~0ull; int bd = -1;
        int p0 = g_rowptr[seed], p1 = g_rowptr[seed + 1];
        for (int p = p0 + lane; p < p1; p += 32) {
            int d = g_csr_dst[p];
            bool in = false;
            #pragma unroll
            for (int j = 0; j < 8; j++) in |= (j < nj) && (joined[j] == (unsigned short)d);
            if (!in) {
                unsigned long long key = g_csr_key[p];
                if (key < bk) { bk = key; bd = d; }
            }
        }
        #pragma unroll
        for (int o = 16; o; o >>= 1) {
            unsigned long long ok = __shfl_down_sync(0xffffffffu, bk, o);
            int od = __shfl_down_sync(0xffffffffu, bd, o);
            if (ok < bk) { bk = ok; bd = od; }
        }
        bk = __shfl_sync(0xffffffffu, bk, 0);
        bd = __shfl_sync(0xffffffffu, bd, 0);
        ck[0] = bk; cd[0] = bd;
    }

    while (tot < 3.0f && nj < 8) {
        unsigned long long bk = ~0ull; int bd = -1;
        #pragma unroll
        for (int r = 0; r < 8; r++) if (r < nj && ck[r] < bk) { bk = ck[r]; bd = cd[r]; }
        if (bd < 0) break;
        tot += __uint_as_float((unsigned)(bk >> 32));
        joined[nj] = (unsigned short)bd;
        nj++;
        // rescan rows whose cached best just joined, and scan the new row
        #pragma unroll
        for (int r = 0; r < 8; r++) {
            if (r < nj && (cd[r] == bd || r == nj - 1)) {
                int u = joined[r];
                unsigned long long nk = ~0ull; int nd = -1;
                int p0 = g_rowptr[u], p1 = g_rowptr[u + 1];
                for (int p = p0 + lane; p < p1; p += 32) {
                    int d = g_csr_dst[p];
                    bool in = false;
                    #pragma unroll
                    for (int j = 0; j < 8; j++) in |= (j < nj) && (joined[j] == (unsigned short)d);
                    if (!in) {
                        unsigned long long key = g_csr_key[p];
                        if (key < nk) { nk = key; nd = d; }
                    }
                }
                #pragma unroll
                for (int o = 16; o; o >>= 1) {
                    unsigned long long ok = __shfl_down_sync(0xffffffffu, nk, o);
                    int od = __shfl_down_sync(0xffffffffu, nd, o);
                    if (ok < nk) { nk = ok; nd = od; }
                }
                nk = __shfl_sync(0xffffffffu, nk, 0);
                nd = __shfl_sync(0xffffffffu, nd, 0);
                ck[r] = nk; cd[r] = nd;
            }
        }
    }

    if (lane == 0) {
        // sort members ascending (0xFFFF sentinels to the end)
        unsigned short memb[8];
        #pragma unroll
        for (int j = 0; j < 8; j++) memb[j] = joined[j];
        #pragma unroll
        for (int a = 0; a < 7; a++)
            #pragma unroll
            for (int b = 0; b < 7 - a; b++) {
                unsigned short x0 = memb[b], x1 = memb[b + 1];
                memb[b] = (x0 < x1) ? x0 : x1;
                memb[b + 1] = (x0 < x1) ? x1 : x0;
            }
        #pragma unroll
        for (int j = 0; j < 8; j++) g_mem[seed][j] = memb[j];
        g_msz[seed] = nj;
        unsigned long long hi = 0, lo = 0;
        #pragma unroll
        for (int j = 0; j < 7; j++) {
            unsigned long long k = (j < nj) ? (unsigned long long)(8191u - memb[j]) : 0ull;
            if (j < 4) hi |= k << (48 - 16 * j);
            else       lo |= k << (48 - 16 * (j - 4));
        }
        g_khi[seed] = hi; g_klo[seed] = lo;   // lo bits [0:16) free
    }
}

// single-block bitonic sort of 4096 128-bit keys (idx packed in lo[0:16)),
// fused with adjacent-dedup + compaction + node->cluster CSR build.
__global__ void k_sort_dedup() {   // <<<1,1024, 65536>>>
    extern __shared__ unsigned long long sk[];   // [2*4096]
    __shared__ int sh[1024];
    int t = threadIdx.x;
    for (int r = t; r < N_NODES; r += 1024) {
        sk[2 * r] = g_khi[r];
        sk[2 * r + 1] = g_klo[r] | (unsigned long long)r;
    }
    __syncthreads();
    for (int k = 2; k <= N_NODES; k <<= 1) {
        for (int j = k >> 1; j > 0; j >>= 1) {
            for (int r = t; r < N_NODES; r += 1024) {
                int x = r ^ j;
                if (x > r) {
                    unsigned long long ah = sk[2 * r], al = sk[2 * r + 1];
                    unsigned long long bh = sk[2 * x], bl = sk[2 * x + 1];
                    bool agtb = (ah > bh) || (ah == bh && al > bl);
                    bool up = ((r & k) == 0);
                    if (agtb == up) {
                        sk[2 * r] = bh; sk[2 * r + 1] = bl;
                        sk[2 * x] = ah; sk[2 * x + 1] = al;
                    }
                }
            }
            __syncthreads();
        }
    }
    // dedup on (hi, lo & ~0xFFFF)
    int fl[4], loc[4];
    int s = 0;
    #pragma unroll
    for (int q = 0; q < 4; q++) {
        int r = t * 4 + q;
        int f;
        if (r == 0) f = 1;
        else {
            unsigned long long ph = sk[2 * (r - 1)], pl = sk[2 * (r - 1) + 1] & ~0xFFFFull;
            unsigned long long ch = sk[2 * r],       cl = sk[2 * r + 1] & ~0xFFFFull;
            f = (ph != ch) || (pl != cl);
        }
        fl[q] = f; loc[q] = s; s += f;
    }
    sh[t] = s; __syncthreads();
    for (int off = 1; off < 1024; off <<= 1) {
        int a = (t >= off) ? sh[t - off] : 0;
        __syncthreads();
        sh[t] += a;
        __syncthreads();
    }
    int pre = t ? sh[t - 1] : 0;
    #pragma unroll
    for (int q = 0; q < 4; q++) {
        int r = t * 4 + q;
        if (fl[q]) {
            int pos = pre + loc[q];
            int src = (int)(sk[2 * r + 1] & 0xFFFFull);
            #pragma unroll
            for (int j = 0; j < 8; j++) g_uniq[pos][j] = g_mem[src][j];
            g_usz[pos] = g_msz[src];
        }
    }
    if (t == 1023) g_U = sh[1023];
    __syncthreads();
    int U = g_U;
    // ---- fused node->cluster CSR build (reuse sk as int scratch) ----
    int* cnt = (int*)sk;               // [0..4096)
    int* ptr = ((int*)sk) + 4096;      // [4096..8193)
    int* fil = ((int*)sk) + 8200;      // [8200..12296)
    for (int i = t; i < N_NODES; i += 1024) cnt[i] = 0;
    __syncthreads();
    for (int u = t; u < U; u += 1024) {
        int sz = g_usz[u];
        for (int mi = 0; mi < sz; mi++) atomicAdd(&cnt[g_uniq[u][mi]], 1);
    }
    __syncthreads();
    {
        int v0 = cnt[t * 4 + 0], v1 = cnt[t * 4 + 1], v2 = cnt[t * 4 + 2], v3 = cnt[t * 4 + 3];
        int ss = v0 + v1 + v2 + v3;
        sh[t] = ss; __syncthreads();
        for (int off = 1; off < 1024; off <<= 1) {
            int a = (t >= off) ? sh[t - off] : 0;
            __syncthreads();
            sh[t] += a;
            __syncthreads();
        }
        int pr = t ? sh[t - 1] : 0;
        ptr[t * 4 + 0] = pr;
        ptr[t * 4 + 1] = pr + v0;
        ptr[t * 4 + 2] = pr + v0 + v1;
        ptr[t * 4 + 3] = pr + v0 + v1 + v2;
        if (t == 1023) ptr[4096] = sh[1023];
    }
    __syncthreads();
    for (int i = t; i <= N_NODES; i += 1024) g_n2uptr[i] = ptr[i];
    for (int i = t; i < N_NODES; i += 1024) fil[i] = 0;
    __syncthreads();
    for (int u = t; u < U; u += 1024) {
        int sz = g_usz[u];
        for (int mi = 0; mi < sz; mi++) {
            int m = g_uniq[u][mi];
            int slot = ptr[m] + atomicAdd(&fil[m], 1);
            g_n2ulist[slot] = u;
        }
    }
}

// ---------------- single-warp bucketed greedy max-cover ----------------
// All state in SMEM. counts <= 7 => 8 count-buckets as 4096-bit bitmaps.
// Repair is the R3-proven idempotent form (clear all b != cc, set cc).
#define G_OFF_CNT   0         // int[4096]
#define G_OFF_PTR   16384     // int[4097]
#define G_OFF_UQ    32784     // u16[4096*8]
#define G_OFF_SZ    98320     // u8[4096]
#define G_OFF_LS    102416    // u16[32768]
#define G_OFF_BKT   167952    // u32[8*128]
#define G_OFF_COV   172048    // u32[128]
#define G_OFF_BEG   172560    // int[8]
#define G_OFF_LEN   172592    // int[8]
#define G_SMEM_TOT  172624

__global__ void k_greedy() {   // <<<1,256, G_SMEM_TOT>>>
    extern __shared__ unsigned char sg[];
    int* s_cnt           = (int*)(sg + G_OFF_CNT);
    int* s_ptr           = (int*)(sg + G_OFF_PTR);
    unsigned short* s_uq = (unsigned short*)(sg + G_OFF_UQ);
    unsigned char* s_sz  = (unsigned char*)(sg + G_OFF_SZ);
    unsigned short* s_ls = (unsigned short*)(sg + G_OFF_LS);
    unsigned* s_bkt      = (unsigned*)(sg + G_OFF_BKT);
    unsigned* s_cov      = (unsigned*)(sg + G_OFF_COV);
    int* s_beg           = (int*)(sg + G_OFF_BEG);
    int* s_len           = (int*)(sg + G_OFF_LEN);

    int t = threadIdx.x;
    int U = g_U;
    int T = g_n2uptr[N_NODES];

    for (int i = t; i < 8 * 128; i += 256) s_bkt[i] = 0;
    for (int i = t; i < 128; i += 256) s_cov[i] = 0;
    __syncthreads();
    for (int c = t; c < N_NODES; c += 256) {
        int cc = (c < U) ? g_usz[c] : 0;
        s_cnt[c] = cc;
        s_sz[c] = (unsigned char)cc;
        ((uint4*)s_uq)[c] = ((const uint4*)g_uniq)[c];
        if (cc > 0) atomicOr(&s_bkt[cc * 128 + (c >> 5)], 1u << (c & 31));
    }
    for (int i = t; i <= N_NODES; i += 256) s_ptr[i] = g_n2uptr[i];
    for (int i = t; i < T; i += 256) s_ls[i] = (unsigned short)g_n2ulist[i];
    __syncthreads();
    if (t >= 32) return;

    int lane = t;
    int covered = 0, K = 0, maxb = 7;
    for (int iter = 0; iter <= N_NODES && covered < N_NODES; iter++) {
        // ---- selection: first-set in highest nonempty bucket ----
        int c = -1;
        while (maxb >= 1) {
            uint4 v4 = ((const uint4*)(s_bkt + maxb * 128))[lane];
            int local = 0x7fffffff;
            if (v4.x) local = min(local, ((lane * 4 + 0) << 5) + __ffs(v4.x) - 1);
            if (v4.y) local = min(local, ((lane * 4 + 1) << 5) + __ffs(v4.y) - 1);
            if (v4.z) local = min(local, ((lane * 4 + 2) << 5) + __ffs(v4.z) - 1);
            if (v4.w) local = min(local, ((lane * 4 + 3) << 5) + __ffs(v4.w) - 1);
            local = __reduce_min_sync(0xffffffffu, local);
            if (local != 0x7fffffff) { c = local; break; }
            maxb--;
        }
        if (c < 0) break;
        if (lane == 0) g_sel[K] = c;
        K++;
        // ---- mark newly covered members (sz <= 7, lane-parallel) ----
        int sz = s_sz[c];
        int m = (lane < sz) ? (int)s_uq[c * 8 + lane] : -1;
        bool isnew = false;
        if (m >= 0) {
            unsigned w = s_cov[m >> 5];
            isnew = !((w >> (m & 31)) & 1u);
        }
        if (isnew) atomicOr(&s_cov[m >> 5], 1u << (m & 31));
        unsigned nb = __ballot_sync(0xffffffffu, isnew);
        int newcnt = __popc(nb);
        covered += newcnt;
        if (isnew) {
            int slot = __popc(nb & ((1u << lane) - 1));
            int b0 = s_ptr[m];
            s_beg[slot] = b0;
            s_len[slot] = s_ptr[m + 1] - b0;
        }
        __syncwarp();
        // register prefix of up to 7 lengths
        int offk[7]; int tot = 0;
        #pragma unroll
        for (int kk = 0; kk < 7; kk++) { offk[kk] = tot; if (kk < newcnt) tot += s_len[kk]; }
        // ---- pass1: all decrements ----
        for (int p = lane; p < tot; p += 32) {
            int kk = 0;
            #pragma unroll
            for (int q = 1; q < 7; q++) if (q < newcnt && p >= offk[q]) kk = q;
            int c2 = (int)s_ls[s_beg[kk] + (p - offk[kk])];
            atomicSub(&s_cnt[c2], 1);
        }
        __syncwarp();
        // ---- pass2: idempotent bucket repair (R3-proven) ----
        for (int p = lane; p < tot; p += 32) {
            int kk = 0;
            #pragma unroll
            for (int q = 1; q < 7; q++) if (q < newcnt && p >= offk[q]) kk = q;
            int c2 = (int)s_ls[s_beg[kk] + (p - offk[kk])];
            int cc = s_cnt[c2];
            unsigned w = c2 >> 5, bit = 1u << (c2 & 31);
            #pragma unroll
            for (int b = 1; b < 8; b++)
                if (b != cc) atomicAnd(&s_bkt[b * 128 + w], ~bit);
            if (cc > 0) atomicOr(&s_bkt[cc * 128 + w], bit);
        }
        __syncwarp();
    }
    if (lane == 0) g_K = K;
}

// fused c2 count + scan + fill (single block)
__global__ void k_c2() {   // <<<1,1024, 49184>>>
    extern __shared__ int sc[];
    int* cnt = sc;            // [0..4096)
    int* ptr = sc + 4096;     // [4096..8193)
    int* fil = sc + 8200;     // [8200..12296)
    __shared__ int sh[1024];
    int t = threadIdx.x;
    int K = g_K;
    for (int i = t; i < N_NODES; i += 1024) cnt[i] = 0;
    __syncthreads();
    for (int k = t; k < K; k += 1024) {
        int c = g_sel[k];
        int sz = g_usz[c];
        for (int mi = 0; mi < sz; mi++) atomicAdd(&cnt[g_uniq[c][mi]], 1);
    }
    __syncthreads();
    {
        int v0 = cnt[t * 4 + 0], v1 = cnt[t * 4 + 1], v2 = cnt[t * 4 + 2], v3 = cnt[t * 4 + 3];
        int ss = v0 + v1 + v2 + v3;
        sh[t] = ss; __syncthreads();
        for (int off = 1; off < 1024; off <<= 1) {
            int a = (t >= off) ? sh[t - off] : 0;
            __syncthreads();
            sh[t] += a;
            __syncthreads();
        }
        int pr = t ? sh[t - 1] : 0;
        ptr[t * 4 + 0] = pr;
        ptr[t * 4 + 1] = pr + v0;
        ptr[t * 4 + 2] = pr + v0 + v1;
        ptr[t * 4 + 3] = pr + v0 + v1 + v2;
        if (t == 1023) ptr[4096] = sh[1023];
    }
    __syncthreads();
    for (int i = t; i <= N_NODES; i += 1024) g_c2ptr[i] = ptr[i];
    for (int i = t; i < N_NODES; i += 1024) fil[i] = 0;
    __syncthreads();
    for (int k = t; k < K; k += 1024) {
        int c = g_sel[k];
        int sz = g_usz[c];
        for (int mi = 0; mi < sz; mi++) {
            int m = g_uniq[c][mi];
            int slot = ptr[m] + atomicAdd(&fil[m], 1);
            g_c2list[slot] = k;
        }
    }
}

__global__ void k_clearB() {
    int tot16 = (g_K * N_NODES) >> 4;
    int stride = gridDim.x * blockDim.x;
    uint4 z = make_uint4(0, 0, 0, 0);
    uint4* B4 = (uint4*)g_B;
    for (int i = blockIdx.x * blockDim.x + threadIdx.x; i < tot16; i += stride)
        B4[i] = z;
}

__global__ void k_markB(const int* __restrict__ ei) {
    int e = blockIdx.x * 256 + threadIdx.x;
    int u = ei[e], v = ei[N_EDGES + e];
    int a0 = g_c2ptr[u], a1 = g_c2ptr[u + 1];
    int b0 = g_c2ptr[v], b1 = g_c2ptr[v + 1];
    for (int p = a0; p < a1; p++) {
        size_t base = (size_t)g_c2list[p] * N_NODES;
        for (int q = b0; q < b1; q++) g_B[base + g_c2list[q]] = 1;
    }
}

// warp-per-row popcount of adjacency rows (limited to K cols)
__global__ void k_rowcnt() {   // <<<512,256>>>
    int gw = (blockIdx.x * blockDim.x + threadIdx.x) >> 5;
    int lane = threadIdx.x & 31;
    if (gw >= N_NODES) return;
    int K = g_K;
    if (gw >= K) { if (lane == 0) g_rn[gw] = 0; return; }
    const unsigned* row = (const unsigned*)(g_B + (size_t)gw * N_NODES);
    int words = (K + 3) >> 2;
    int c = 0;
    for (int j = lane; j < words; j += 32) c += __popc(row[j]);
    #pragma unroll
    for (int o = 16; o; o >>= 1) c += __shfl_down_sync(0xffffffffu, c, o);
    if (lane == 0) g_rn[gw] = c - (int)g_B[(size_t)gw * N_NODES + gw];
}

// warp-per-row ballot compaction into the edge list
__global__ void k_write_edges(float* __restrict__ out) {   // <<<512,256>>>
    int gw = (blockIdx.x * blockDim.x + threadIdx.x) >> 5;
    int lane = threadIdx.x & 31;
    if (gw >= N_NODES) return;
    int K = g_K;
    if (gw >= K) return;
    int nnz = g_roff[K];
    const unsigned char* row = g_B + (size_t)gw * N_NODES;
    int p = g_roff[gw];
    for (int base = 0; base < K; base += 32) {
        int j = base + lane;
        bool v = (j < K) && (j != gw) && (row[j] != 0);
        unsigned m = __ballot_sync(0xffffffffu, v);
        if (v) {
            int off = __popc(m & ((1u << lane) - 1));
            out[p + off] = (float)gw;
            out[nnz + p + off] = (float)j;
        }
        p += __popc(m);
    }
}

// fused outputs: S rows, Ms rows, x_new, edge_index copy
__global__ void k_outputs(const float* __restrict__ x, const int* __restrict__ ei,
                          float* __restrict__ out) {   // <<<8704,256>>>
    int b = blockIdx.x, t = threadIdx.x;
    int K = g_K;
    int nnz = g_roff[K];
    size_t offX = 2 * (size_t)nnz;
    size_t offS = offX + (size_t)K * D_FEAT;
    size_t offM = offS + (size_t)K * N_NODES;
    size_t offE = offM + (size_t)K * N_NODES;
    if (b < 4096) {
        if (b >= K) return;
        int c = g_sel[b];
        int sz = g_usz[c];
        unsigned short mb[8];
        #pragma unroll
        for (int j = 0; j < 8; j++) mb[j] = (j < sz) ? g_uniq[c][j] : 0xFFFF;
        size_t baseS = offS + (size_t)b * N_NODES;
        size_t baseM = offM + (size_t)b * N_NODES;
        for (int j = t; j < N_NODES; j += 256) {
            bool in = false;
            #pragma unroll
            for (int q = 0; q < 8; q++) in |= (mb[q] == (unsigned short)j);
            float mv = in ? g_avg[j] : 0.f;
            out[baseS + j] = in ? 1.f : 0.f;
            out[baseM + j] = mv;
        }
    } else if (b < 8192) {
        int k = b - 4096;
        if (k >= K) return;
        int c = g_sel[k];
        int sz = g_usz[c];
        float acc = 0.f;
        for (int mi = 0; mi < sz; mi++) {
            int m = g_uniq[c][mi];
            acc += g_avg[m] * x[(size_t)m * D_FEAT + t];
        }
        out[offX + (size_t)k * D_FEAT + t] = acc;
    } else {
        int i = (b - 8192) * 256 + t;
        out[offE + i] = (float)ei[i];
    }
}

// ------------------------- launch -------------------------
extern "C" void kernel_launch(void* const* d_in, const int* in_sizes, int n_in,
                              void* d_out, int out_size) {
    const float* x  = (const float*)d_in[0];
    const int*   ei = (const int*)d_in[1];
    float*       out = (float*)d_out;
    cudaStream_t st = cudaStreamPerThread;

    cudaFuncSetAttribute(k_sort_dedup, cudaFuncAttributeMaxDynamicSharedMemorySize, 65536);
    cudaFuncSetAttribute(k_greedy, cudaFuncAttributeMaxDynamicSharedMemorySize, G_SMEM_TOT);
    cudaFuncSetAttribute(k_c2, cudaFuncAttributeMaxDynamicSharedMemorySize, 49184);

    k_init       <<<16, 256, 0, st>>>();
    k_dist       <<<N_EDGES / 8, 256, 0, st>>>(x, ei);
    k_scan4096   <<<1, 1024, 0, st>>>(0);            // deg -> rowptr
    k_norm_fill  <<<N_EDGES / 256, 256, 0, st>>>(ei);
    k_avg        <<<16, 256, 0, st>>>();
    k_grow       <<<512, 256, 0, st>>>();
    k_sort_dedup <<<1, 1024, 65536, st>>>();
    k_greedy     <<<1, 256, G_SMEM_TOT, st>>>();
    k_c2         <<<1, 1024, 49184, st>>>();
    k_clearB     <<<512, 256, 0, st>>>();
    k_markB      <<<N_EDGES / 256, 256, 0, st>>>(ei);
    k_rowcnt     <<<512, 256, 0, st>>>();
    k_scan4096   <<<1, 1024, 0, st>>>(1);            // rn -> roff
    k_write_edges<<<512, 256, 0, st>>>(out);
    k_outputs    <<<8704, 256, 0, st>>>(x, ei, out);
}

// round 8
// speedup vs baseline: 3.0576x; 1.1763x over previous
#include <cuda_runtime.h>
#include <cstdint>

#define N_NODES 4096
#define D_FEAT  256
#define N_EDGES 65536

// ------------------------- static device scratch -------------------------
static __device__ float g_sraw[N_EDGES];
static __device__ unsigned g_minb, g_maxb;
static __device__ int   g_deg[N_NODES];
static __device__ int   g_rowptr[N_NODES + 1];
static __device__ int   g_fill[N_NODES];
static __device__ unsigned long long g_csr_key[N_EDGES];   // (score_bits<<32)|eid
static __device__ int   g_csr_dst[N_EDGES];
static __device__ float g_tot[N_NODES];
static __device__ int   g_cntN[N_NODES];
static __device__ float g_avg[N_NODES];
static __device__ __align__(16) unsigned short g_mem[N_NODES][8];
static __device__ int   g_msz[N_NODES];
static __device__ unsigned long long g_khi[N_NODES], g_klo[N_NODES];
static __device__ __align__(16) unsigned short g_uniq[N_NODES][8];
static __device__ int   g_usz[N_NODES];
static __device__ int   g_U;
static __device__ int   g_n2uptr[N_NODES + 1];
static __device__ int   g_n2ulist[N_NODES * 8];
static __device__ int   g_sel[N_NODES];
static __device__ int   g_K;
static __device__ int   g_c2ptr[N_NODES + 1];
static __device__ int   g_c2list[N_NODES * 8];
static __device__ unsigned char g_B[(size_t)N_NODES * N_NODES];   // cluster adj bitmap
static __device__ int   g_rn[N_NODES], g_roff[N_NODES + 1];

// ------------------------- kernels -------------------------

__global__ void k_init() {
    int i = blockIdx.x * blockDim.x + threadIdx.x;
    if (i < N_NODES) {
        g_deg[i] = 0; g_fill[i] = 0;
        g_tot[i] = 0.f; g_cntN[i] = 0;
    }
    if (i == 0) { g_minb = 0x7f800000u; g_maxb = 0u; }
}

// one warp per edge: fp32 distance (float4 loads), degree count, global min/max
__global__ void k_dist(const float* __restrict__ x, const int* __restrict__ ei) {
    int warp = threadIdx.x >> 5, lane = threadIdx.x & 31;
    int e = blockIdx.x * 8 + warp;
    __shared__ float smin[8], smax[8];
    float sval = __int_as_float(0x7f800000);
    {
        int u = ei[e], v = ei[N_EDGES + e];
        const float4* xu = (const float4*)(x + (size_t)u * D_FEAT);
        const float4* xv = (const float4*)(x + (size_t)v * D_FEAT);
        float acc = 0.f;
        #pragma unroll
        for (int i = 0; i < 2; i++) {
            float4 a = xu[lane + 32 * i], b = xv[lane + 32 * i];
            float d0 = a.x - b.x, d1 = a.y - b.y, d2 = a.z - b.z, d3 = a.w - b.w;
            acc = fmaf(d0, d0, acc);
            acc = fmaf(d1, d1, acc);
            acc = fmaf(d2, d2, acc);
            acc = fmaf(d3, d3, acc);
        }
        #pragma unroll
        for (int o = 16; o; o >>= 1) acc += __shfl_down_sync(0xffffffffu, acc, o);
        if (lane == 0) {
            float s = sqrtf(acc + 1e-12f);
            g_sraw[e] = s;
            atomicAdd(&g_deg[u], 1);
            sval = s;
        }
    }
    if (lane == 0) { smin[warp] = sval; smax[warp] = sval; }
    __syncthreads();
    if (threadIdx.x == 0) {
        float mn = smin[0], mx = smax[0];
        #pragma unroll
        for (int i = 1; i < 8; i++) { mn = fminf(mn, smin[i]); mx = fmaxf(mx, smax[i]); }
        atomicMin(&g_minb, __float_as_uint(mn));
        atomicMax(&g_maxb, __float_as_uint(mx));
    }
}

// exclusive scan of a fixed 4096-int array selected by `which`
__global__ void k_scan4096(int which) {
    const int* in; int* out;
    if (which == 0) { in = g_deg; out = g_rowptr; }
    else            { in = g_rn;  out = g_roff;   }
    __shared__ int sh[1024];
    int t = threadIdx.x;
    int v0 = in[t * 4 + 0], v1 = in[t * 4 + 1], v2 = in[t * 4 + 2], v3 = in[t * 4 + 3];
    int s = v0 + v1 + v2 + v3;
    sh[t] = s; __syncthreads();
    for (int off = 1; off < 1024; off <<= 1) {
        int a = (t >= off) ? sh[t - off] : 0;
        __syncthreads();
        sh[t] += a;
        __syncthreads();
    }
    int pre = t ? sh[t - 1] : 0;
    out[t * 4 + 0] = pre;
    out[t * 4 + 1] = pre + v0;
    out[t * 4 + 2] = pre + v0 + v1;
    out[t * 4 + 3] = pre + v0 + v1 + v2;
    if (t == 1023) out[4096] = sh[1023];
}

__global__ void k_norm_fill(const int* __restrict__ ei) {
    int e = blockIdx.x * 256 + threadIdx.x;
    float mn = __uint_as_float(g_minb), mx = __uint_as_float(g_maxb);
    float s = (g_sraw[e] - mn) / (mx - mn) + 0.5f;
    int u = ei[e], v = ei[N_EDGES + e];
    atomicAdd(&g_tot[u], s); atomicAdd(&g_tot[v], s);
    atomicAdd(&g_cntN[u], 1); atomicAdd(&g_cntN[v], 1);
    int slot = g_rowptr[u] + atomicAdd(&g_fill[u], 1);
    g_csr_key[slot] = ((unsigned long long)__float_as_uint(s) << 32) | (unsigned)e;
    g_csr_dst[slot] = v;
}

__global__ void k_avg() {
    int i = blockIdx.x * blockDim.x + threadIdx.x;
    if (i < N_NODES) g_avg[i] = g_tot[i] / (float)g_cntN[i];
}

// warp-per-seed Prim-style growth with per-row cached best candidates.
// A cached row-min only invalidates when its dst joins the cluster.
__global__ void __launch_bounds__(256) k_grow() {   // <<<512,256>>>
    int wid = threadIdx.x >> 5, lane = threadIdx.x & 31;
    int seed = blockIdx.x * 8 + wid;
    unsigned short joined[8];
    unsigned long long ck[8];
    int cd[8];
    #pragma unroll
    for (int j = 0; j < 8; j++) { joined[j] = 0xFFFF; ck[j] = ~0ull; cd[j] = -1; }
    joined[0] = (unsigned short)seed;
    int nj = 1; float tot = 0.f;

    // initial scan of seed row
    {
        unsigned long long bk = ~0ull; int bd = -1;
        int p0 = g_rowptr[seed], p1 = g_rowptr[seed + 1];
        for (int p = p0 + lane; p < p1; p += 32) {
            int d = g_csr_dst[p];
            bool in = false;
            #pragma unroll
            for (int j = 0; j < 8; j++) in |= (j < nj) && (joined[j] == (unsigned short)d);
            if (!in) {
                unsigned long long key = g_csr_key[p];
                if (key < bk) { bk = key; bd = d; }
            }
        }
        #pragma unroll
        for (int o = 16; o; o >>= 1) {
            unsigned long long ok = __shfl_down_sync(0xffffffffu, bk, o);
            int od = __shfl_down_sync(0xffffffffu, bd, o);
            if (ok < bk) { bk = ok; bd = od; }
        }
        bk = __shfl_sync(0xffffffffu, bk, 0);
        bd = __shfl_sync(0xffffffffu, bd, 0);
        ck[0] = bk; cd[0] = bd;
    }

    while (tot < 3.0f && nj < 8) {
        unsigned long long bk = ~0ull; int bd = -1;
        #pragma unroll
        for (int r = 0; r < 8; r++) if (r < nj && ck[r] < bk) { bk = ck[r]; bd = cd[r]; }
        if (bd < 0) break;
        tot += __uint_as_float((unsigned)(bk >> 32));
        joined[nj] = (unsigned short)bd;
        nj++;
        // rescan rows whose cached best just joined, and scan the new row
        #pragma unroll
        for (int r = 0; r < 8; r++) {
            if (r < nj && (cd[r] == bd || r == nj - 1)) {
                int u = joined[r];
                unsigned long long nk = ~0ull; int nd = -1;
                int p0 = g_rowptr[u], p1 = g_rowptr[u + 1];
                for (int p = p0 + lane; p < p1; p += 32) {
                    int d = g_csr_dst[p];
                    bool in = false;
                    #pragma unroll
                    for (int j = 0; j < 8; j++) in |= (j < nj) && (joined[j] == (unsigned short)d);
                    if (!in) {
                        unsigned long long key = g_csr_key[p];
                        if (key < nk) { nk = key; nd = d; }
                    }
                }
                #pragma unroll
                for (int o = 16; o; o >>= 1) {
                    unsigned long long ok = __shfl_down_sync(0xffffffffu, nk, o);
                    int od = __shfl_down_sync(0xffffffffu, nd, o);
                    if (ok < nk) { nk = ok; nd = od; }
                }
                nk = __shfl_sync(0xffffffffu, nk, 0);
                nd = __shfl_sync(0xffffffffu, nd, 0);
                ck[r] = nk; cd[r] = nd;
            }
        }
    }

    if (lane == 0) {
        // sort members ascending (0xFFFF sentinels to the end)
        unsigned short memb[8];
        #pragma unroll
        for (int j = 0; j < 8; j++) memb[j] = joined[j];
        #pragma unroll
        for (int a = 0; a < 7; a++)
            #pragma unroll
            for (int b = 0; b < 7 - a; b++) {
                unsigned short x0 = memb[b], x1 = memb[b + 1];
                memb[b] = (x0 < x1) ? x0 : x1;
                memb[b + 1] = (x0 < x1) ? x1 : x0;
            }
        #pragma unroll
        for (int j = 0; j < 8; j++) g_mem[seed][j] = memb[j];
        g_msz[seed] = nj;
        unsigned long long hi = 0, lo = 0;
        #pragma unroll
        for (int j = 0; j < 7; j++) {
            unsigned long long k = (j < nj) ? (unsigned long long)(8191u - memb[j]) : 0ull;
            if (j < 4) hi |= k << (48 - 16 * j);
            else       lo |= k << (48 - 16 * (j - 4));
        }
        g_khi[seed] = hi; g_klo[seed] = lo;   // lo bits [0:16) free
    }
}

// single-block bitonic sort of 4096 128-bit keys (idx packed in lo[0:16)),
// fused with adjacent-dedup + compaction + node->cluster CSR build.
__global__ void k_sort_dedup() {   // <<<1,1024, 65536>>>
    extern __shared__ unsigned long long sk[];   // [2*4096]
    __shared__ int sh[1024];
    int t = threadIdx.x;
    for (int r = t; r < N_NODES; r += 1024) {
        sk[2 * r] = g_khi[r];
        sk[2 * r + 1] = g_klo[r] | (unsigned long long)r;
    }
    __syncthreads();
    for (int k = 2; k <= N_NODES; k <<= 1) {
        for (int j = k >> 1; j > 0; j >>= 1) {
            for (int r = t; r < N_NODES; r += 1024) {
                int x = r ^ j;
                if (x > r) {
                    unsigned long long ah = sk[2 * r], al = sk[2 * r + 1];
                    unsigned long long bh = sk[2 * x], bl = sk[2 * x + 1];
                    bool agtb = (ah > bh) || (ah == bh && al > bl);
                    bool up = ((r & k) == 0);
                    if (agtb == up) {
                        sk[2 * r] = bh; sk[2 * r + 1] = bl;
                        sk[2 * x] = ah; sk[2 * x + 1] = al;
                    }
                }
            }
            __syncthreads();
        }
    }
    // dedup on (hi, lo & ~0xFFFF)
    int fl[4], loc[4];
    int s = 0;
    #pragma unroll
    for (int q = 0; q < 4; q++) {
        int r = t * 4 + q;
        int f;
        if (r == 0) f = 1;
        else {
            unsigned long long ph = sk[2 * (r - 1)], pl = sk[2 * (r - 1) + 1] & ~0xFFFFull;
            unsigned long long ch = sk[2 * r],       cl = sk[2 * r + 1] & ~0xFFFFull;
            f = (ph != ch) || (pl != cl);
        }
        fl[q] = f; loc[q] = s; s += f;
    }
    sh[t] = s; __syncthreads();
    for (int off = 1; off < 1024; off <<= 1) {
        int a = (t >= off) ? sh[t - off] : 0;
        __syncthreads();
        sh[t] += a;
        __syncthreads();
    }
    int pre = t ? sh[t - 1] : 0;
    #pragma unroll
    for (int q = 0; q < 4; q++) {
        int r = t * 4 + q;
        if (fl[q]) {
            int pos = pre + loc[q];
            int src = (int)(sk[2 * r + 1] & 0xFFFFull);
            #pragma unroll
            for (int j = 0; j < 8; j++) g_uniq[pos][j] = g_mem[src][j];
            g_usz[pos] = g_msz[src];
        }
    }
    if (t == 1023) g_U = sh[1023];
    __syncthreads();
    int U = g_U;
    // ---- fused node->cluster CSR build (reuse sk as int scratch) ----
    int* cnt = (int*)sk;               // [0..4096)
    int* ptr = ((int*)sk) + 4096;      // [4096..8193)
    int* fil = ((int*)sk) + 8200;      // [8200..12296)
    for (int i = t; i < N_NODES; i += 1024) cnt[i] = 0;
    __syncthreads();
    for (int u = t; u < U; u += 1024) {
        int sz = g_usz[u];
        for (int mi = 0; mi < sz; mi++) atomicAdd(&cnt[g_uniq[u][mi]], 1);
    }
    __syncthreads();
    {
        int v0 = cnt[t * 4 + 0], v1 = cnt[t * 4 + 1], v2 = cnt[t * 4 + 2], v3 = cnt[t * 4 + 3];
        int ss = v0 + v1 + v2 + v3;
        sh[t] = ss; __syncthreads();
        for (int off = 1; off < 1024; off <<= 1) {
            int a = (t >= off) ? sh[t - off] : 0;
            __syncthreads();
            sh[t] += a;
            __syncthreads();
        }
        int pr = t ? sh[t - 1] : 0;
        ptr[t * 4 + 0] = pr;
        ptr[t * 4 + 1] = pr + v0;
        ptr[t * 4 + 2] = pr + v0 + v1;
        ptr[t * 4 + 3] = pr + v0 + v1 + v2;
        if (t == 1023) ptr[4096] = sh[1023];
    }
    __syncthreads();
    for (int i = t; i <= N_NODES; i += 1024) g_n2uptr[i] = ptr[i];
    for (int i = t; i < N_NODES; i += 1024) fil[i] = 0;
    __syncthreads();
    for (int u = t; u < U; u += 1024) {
        int sz = g_usz[u];
        for (int mi = 0; mi < sz; mi++) {
            int m = g_uniq[u][mi];
            int slot = ptr[m] + atomicAdd(&fil[m], 1);
            g_n2ulist[slot] = u;
        }
    }
}

// ---------------- single-warp greedy max-cover, monotone-key scheme ----------------
// key[c] = (uncovered_cnt << 12) | (4095 - c).  Decrement = one exact atomicSub.
// Selection = max over 128 group maxima; touched groups recomputed lane-parallel.
#define G_OFF_KEY   0         // u32[4096]
#define G_OFF_PTR   16384     // int[4097] (pad to 16400)
#define G_OFF_UQ    32784     // u16[4096*8]
#define G_OFF_SZ    98320     // u8[4096]
#define G_OFF_LS    102416    // u16[32768]
#define G_OFF_GMX   167952    // u32[128]
#define G_OFF_COV   168464    // u32[128]
#define G_OFF_BEG   168976    // int[8]
#define G_OFF_LEN   169008    // int[8]
#define G_SMEM_TOT  169040

__device__ __forceinline__ unsigned g_group_max(const unsigned* key, int g) {
    const uint4* k4 = (const uint4*)(key + g * 32);
    unsigned m = 0;
    #pragma unroll
    for (int i = 0; i < 8; i++) {
        uint4 v = k4[i];
        m = max(m, max(max(v.x, v.y), max(v.z, v.w)));
    }
    return m;
}

__global__ void k_greedy() {   // <<<1,256, G_SMEM_TOT>>>
    extern __shared__ unsigned char sg[];
    unsigned* s_key      = (unsigned*)(sg + G_OFF_KEY);
    int* s_ptr           = (int*)(sg + G_OFF_PTR);
    unsigned short* s_uq = (unsigned short*)(sg + G_OFF_UQ);
    unsigned char* s_sz  = (unsigned char*)(sg + G_OFF_SZ);
    unsigned short* s_ls = (unsigned short*)(sg + G_OFF_LS);
    unsigned* s_gmx      = (unsigned*)(sg + G_OFF_GMX);
    unsigned* s_cov      = (unsigned*)(sg + G_OFF_COV);
    int* s_beg           = (int*)(sg + G_OFF_BEG);
    int* s_len           = (int*)(sg + G_OFF_LEN);

    int t = threadIdx.x;
    int U = g_U;
    int T = g_n2uptr[N_NODES];

    for (int i = t; i < 128; i += 256) s_cov[i] = 0;
    for (int c = t; c < N_NODES; c += 256) {
        int cc = (c < U) ? g_usz[c] : 0;
        s_key[c] = ((unsigned)cc << 12) | (unsigned)(4095 - c);
        s_sz[c] = (unsigned char)cc;
        ((uint4*)s_uq)[c] = ((const uint4*)g_uniq)[c];
    }
    for (int i = t; i <= N_NODES; i += 256) s_ptr[i] = g_n2uptr[i];
    for (int i = t; i < T; i += 256) s_ls[i] = (unsigned short)g_n2ulist[i];
    __syncthreads();
    if (t < 128) s_gmx[t] = g_group_max(s_key, t);
    __syncthreads();
    if (t >= 32) return;

    int lane = t;
    int covered = 0, K = 0;
    for (int iter = 0; iter < N_NODES && covered < N_NODES; iter++) {
        // ---- selection: global max of group maxima ----
        uint4 gm4 = ((const uint4*)s_gmx)[lane];
        unsigned best = max(max(gm4.x, gm4.y), max(gm4.z, gm4.w));
        best = __reduce_max_sync(0xffffffffu, best);
        if (best < 4096u) break;     // all counts zero
        int c = 4095 - (int)(best & 4095u);
        if (lane == 0) g_sel[K & (N_NODES - 1)] = c;
        K++;
        // ---- mark newly covered members (sz <= 7, lane-parallel) ----
        int sz = s_sz[c];
        int m = (lane < sz) ? (int)s_uq[c * 8 + lane] : -1;
        bool isnew = false;
        if (m >= 0) {
            unsigned w = s_cov[m >> 5];
            isnew = !((w >> (m & 31)) & 1u);
        }
        if (isnew) atomicOr(&s_cov[m >> 5], 1u << (m & 31));
        unsigned nb = __ballot_sync(0xffffffffu, isnew);
        int newcnt = __popc(nb);
        covered += newcnt;
        if (isnew) {
            int slot = __popc(nb & ((1u << lane) - 1));
            int b0 = s_ptr[m];
            s_beg[slot] = b0;
            s_len[slot] = s_ptr[m + 1] - b0;
        }
        __syncwarp();
        // register prefix of up to 7 lengths
        int offk[7]; int tot = 0;
        #pragma unroll
        for (int kk = 0; kk < 7; kk++) { offk[kk] = tot; if (kk < newcnt) tot += s_len[kk]; }
        // ---- pass1: exact decrements ----
        for (int p = lane; p < tot; p += 32) {
            int kk = 0;
            #pragma unroll
            for (int q = 1; q < 7; q++) if (q < newcnt && p >= offk[q]) kk = q;
            int c2 = (int)s_ls[s_beg[kk] + (p - offk[kk])];
            atomicSub(&s_key[c2], 4096u);
        }
        __syncwarp();
        // ---- pass2: recompute group maxima of touched groups (idempotent) ----
        for (int p = lane; p < tot; p += 32) {
            int kk = 0;
            #pragma unroll
            for (int q = 1; q < 7; q++) if (q < newcnt && p >= offk[q]) kk = q;
            int c2 = (int)s_ls[s_beg[kk] + (p - offk[kk])];
            int g = c2 >> 5;
            s_gmx[g] = g_group_max(s_key, g);
        }
        __syncwarp();
    }
    if (lane == 0) g_K = K;
}

// fused c2 count + scan + fill (single block)
__global__ void k_c2() {   // <<<1,1024, 49184>>>
    extern __shared__ int sc[];
    int* cnt = sc;            // [0..4096)
    int* ptr = sc + 4096;     // [4096..8193)
    int* fil = sc + 8200;     // [8200..12296)
    __shared__ int sh[1024];
    int t = threadIdx.x;
    int K = g_K;
    for (int i = t; i < N_NODES; i += 1024) cnt[i] = 0;
    __syncthreads();
    for (int k = t; k < K; k += 1024) {
        int c = g_sel[k];
        int sz = g_usz[c];
        for (int mi = 0; mi < sz; mi++) atomicAdd(&cnt[g_uniq[c][mi]], 1);
    }
    __syncthreads();
    {
        int v0 = cnt[t * 4 + 0], v1 = cnt[t * 4 + 1], v2 = cnt[t * 4 + 2], v3 = cnt[t * 4 + 3];
        int ss = v0 + v1 + v2 + v3;
        sh[t] = ss; __syncthreads();
        for (int off = 1; off < 1024; off <<= 1) {
            int a = (t >= off) ? sh[t - off] : 0;
            __syncthreads();
            sh[t] += a;
            __syncthreads();
        }
        int pr = t ? sh[t - 1] : 0;
        ptr[t * 4 + 0] = pr;
        ptr[t * 4 + 1] = pr + v0;
        ptr[t * 4 + 2] = pr + v0 + v1;
        ptr[t * 4 + 3] = pr + v0 + v1 + v2;
        if (t == 1023) ptr[4096] = sh[1023];
    }
    __syncthreads();
    for (int i = t; i <= N_NODES; i += 1024) g_c2ptr[i] = ptr[i];
    for (int i = t; i < N_NODES; i += 1024) fil[i] = 0;
    __syncthreads();
    for (int k = t; k < K; k += 1024) {
        int c = g_sel[k];
        int sz = g_usz[c];
        for (int mi = 0; mi < sz; mi++) {
            int m = g_uniq[c][mi];
            int slot = ptr[m] + atomicAdd(&fil[m], 1);
            g_c2list[slot] = k;
        }
    }
}

__global__ void k_clearB() {
    int tot16 = (g_K * N_NODES) >> 4;
    int stride = gridDim.x * blockDim.x;
    uint4 z = make_uint4(0, 0, 0, 0);
    uint4* B4 = (uint4*)g_B;
    for (int i = blockIdx.x * blockDim.x + threadIdx.x; i < tot16; i += stride)
        B4[i] = z;
}

__global__ void k_markB(const int* __restrict__ ei) {
    int e = blockIdx.x * 256 + threadIdx.x;
    int u = ei[e], v = ei[N_EDGES + e];
    int a0 = g_c2ptr[u], a1 = g_c2ptr[u + 1];
    int b0 = g_c2ptr[v], b1 = g_c2ptr[v + 1];
    for (int p = a0; p < a1; p++) {
        size_t base = (size_t)g_c2list[p] * N_NODES;
        for (int q = b0; q < b1; q++) g_B[base + g_c2list[q]] = 1;
    }
}

// warp-per-row popcount of adjacency rows (limited to K cols)
__global__ void k_rowcnt() {   // <<<512,256>>>
    int gw = (blockIdx.x * blockDim.x + threadIdx.x) >> 5;
    int lane = threadIdx.x & 31;
    if (gw >= N_NODES) return;
    int K = g_K;
    if (gw >= K) { if (lane == 0) g_rn[gw] = 0; return; }
    const unsigned* row = (const unsigned*)(g_B + (size_t)gw * N_NODES);
    int words = (K + 3) >> 2;
    int c = 0;
    for (int j = lane; j < words; j += 32) c += __popc(row[j]);
    #pragma unroll
    for (int o = 16; o; o >>= 1) c += __shfl_down_sync(0xffffffffu, c, o);
    if (lane == 0) g_rn[gw] = c - (int)g_B[(size_t)gw * N_NODES + gw];
}

// warp-per-row ballot compaction into the edge list
__global__ void k_write_edges(float* __restrict__ out) {   // <<<512,256>>>
    int gw = (blockIdx.x * blockDim.x + threadIdx.x) >> 5;
    int lane = threadIdx.x & 31;
    if (gw >= N_NODES) return;
    int K = g_K;
    if (gw >= K) return;
    int nnz = g_roff[K];
    const unsigned char* row = g_B + (size_t)gw * N_NODES;
    int p = g_roff[gw];
    for (int base = 0; base < K; base += 32) {
        int j = base + lane;
        bool v = (j < K) && (j != gw) && (row[j] != 0);
        unsigned m = __ballot_sync(0xffffffffu, v);
        if (v) {
            int off = __popc(m & ((1u << lane) - 1));
            out[p + off] = (float)gw;
            out[nnz + p + off] = (float)j;
        }
        p += __popc(m);
    }
}

// fused outputs: S rows, Ms rows, x_new, edge_index copy
__global__ void k_outputs(const float* __restrict__ x, const int* __restrict__ ei,
                          float* __restrict__ out) {   // <<<8704,256>>>
    int b = blockIdx.x, t = threadIdx.x;
    int K = g_K;
    int nnz = g_roff[K];
    size_t offX = 2 * (size_t)nnz;
    size_t offS = offX + (size_t)K * D_FEAT;
    size_t offM = offS + (size_t)K * N_NODES;
    size_t offE = offM + (size_t)K * N_NODES;
    if (b < 4096) {
        if (b >= K) return;
        int c = g_sel[b];
        int sz = g_usz[c];
        unsigned short mb[8];
        #pragma unroll
        for (int j = 0; j < 8; j++) mb[j] = (j < sz) ? g_uniq[c][j] : 0xFFFF;
        size_t baseS = offS + (size_t)b * N_NODES;
        size_t baseM = offM + (size_t)b * N_NODES;
        for (int j = t; j < N_NODES; j += 256) {
            bool in = false;
            #pragma unroll
            for (int q = 0; q < 8; q++) in |= (mb[q] == (unsigned short)j);
            float mv = in ? g_avg[j] : 0.f;
            out[baseS + j] = in ? 1.f : 0.f;
            out[baseM + j] = mv;
        }
    } else if (b < 8192) {
        int k = b - 4096;
        if (k >= K) return;
        int c = g_sel[k];
        int sz = g_usz[c];
        float acc = 0.f;
        for (int mi = 0; mi < sz; mi++) {
            int m = g_uniq[c][mi];
            acc += g_avg[m] * x[(size_t)m * D_FEAT + t];
        }
        out[offX + (size_t)k * D_FEAT + t] = acc;
    } else {
        int i = (b - 8192) * 256 + t;
        out[offE + i] = (float)ei[i];
    }
}

// ------------------------- launch -------------------------
extern "C" void kernel_launch(void* const* d_in, const int* in_sizes, int n_in,
                              void* d_out, int out_size) {
    const float* x  = (const float*)d_in[0];
    const int*   ei = (const int*)d_in[1];
    float*       out = (float*)d_out;
    cudaStream_t st = cudaStreamPerThread;

    cudaFuncSetAttribute(k_sort_dedup, cudaFuncAttributeMaxDynamicSharedMemorySize, 65536);
    cudaFuncSetAttribute(k_greedy, cudaFuncAttributeMaxDynamicSharedMemorySize, G_SMEM_TOT);
    cudaFuncSetAttribute(k_c2, cudaFuncAttributeMaxDynamicSharedMemorySize, 49184);

    k_init       <<<16, 256, 0, st>>>();
    k_dist       <<<N_EDGES / 8, 256, 0, st>>>(x, ei);
    k_scan4096   <<<1, 1024, 0, st>>>(0);            // deg -> rowptr
    k_norm_fill  <<<N_EDGES / 256, 256, 0, st>>>(ei);
    k_avg        <<<16, 256, 0, st>>>();
    k_grow       <<<512, 256, 0, st>>>();
    k_sort_dedup <<<1, 1024, 65536, st>>>();
    k_greedy     <<<1, 256, G_SMEM_TOT, st>>>();
    k_c2         <<<1, 1024, 49184, st>>>();
    k_clearB     <<<512, 256, 0, st>>>();
    k_markB      <<<N_EDGES / 256, 256, 0, st>>>(ei);
    k_rowcnt     <<<512, 256, 0, st>>>();
    k_scan4096   <<<1, 1024, 0, st>>>(1);            // rn -> roff
    k_write_edges<<<512, 256, 0, st>>>(out);
    k_outputs    <<<8704, 256, 0, st>>>(x, ei, out);
}

// round 9
// speedup vs baseline: 4.2200x; 1.3802x over previous
#include <cuda_runtime.h>
#include <cstdint>

#define N_NODES 4096
#define D_FEAT  256
#define N_EDGES 65536

// ------------------------- static device scratch -------------------------
static __device__ float g_sraw[N_EDGES];
static __device__ unsigned g_minb, g_maxb;
static __device__ int   g_deg[N_NODES];
static __device__ int   g_rowptr[N_NODES + 1];
static __device__ int   g_fill[N_NODES];
static __device__ unsigned long long g_csr_key[N_EDGES];   // (score_bits<<32)|eid
static __device__ int   g_csr_dst[N_EDGES];
static __device__ float g_tot[N_NODES];
static __device__ int   g_cntN[N_NODES];
static __device__ float g_avg[N_NODES];
static __device__ __align__(16) unsigned short g_mem[N_NODES][8];
static __device__ int   g_msz[N_NODES];
static __device__ unsigned long long g_khi[N_NODES], g_klo[N_NODES];
static __device__ __align__(16) unsigned short g_uniq[N_NODES][8];
static __device__ int   g_usz[N_NODES];
static __device__ int   g_U;
static __device__ int   g_n2uptr[N_NODES + 1];
static __device__ int   g_n2ulist[N_NODES * 8];
static __device__ int   g_sel[N_NODES];
static __device__ int   g_K;
static __device__ int   g_c2ptr[N_NODES + 1];
static __device__ int   g_c2list[N_NODES * 8];
static __device__ unsigned char g_B[(size_t)N_NODES * N_NODES];   // cluster adj bitmap
static __device__ int   g_rn[N_NODES], g_roff[N_NODES + 1];

// ------------------------- kernels -------------------------

__global__ void k_init() {
    int i = blockIdx.x * blockDim.x + threadIdx.x;
    if (i < N_NODES) {
        g_deg[i] = 0; g_fill[i] = 0;
        g_tot[i] = 0.f; g_cntN[i] = 0;
    }
    if (i == 0) { g_minb = 0x7f800000u; g_maxb = 0u; }
}

// one warp per edge: fp32 distance (float4 loads), degree count, global min/max
__global__ void k_dist(const float* __restrict__ x, const int* __restrict__ ei) {
    int warp = threadIdx.x >> 5, lane = threadIdx.x & 31;
    int e = blockIdx.x * 8 + warp;
    __shared__ float smin[8], smax[8];
    float sval = __int_as_float(0x7f800000);
    {
        int u = ei[e], v = ei[N_EDGES + e];
        const float4* xu = (const float4*)(x + (size_t)u * D_FEAT);
        const float4* xv = (const float4*)(x + (size_t)v * D_FEAT);
        float acc = 0.f;
        #pragma unroll
        for (int i = 0; i < 2; i++) {
            float4 a = xu[lane + 32 * i], b = xv[lane + 32 * i];
            float d0 = a.x - b.x, d1 = a.y - b.y, d2 = a.z - b.z, d3 = a.w - b.w;
            acc = fmaf(d0, d0, acc);
            acc = fmaf(d1, d1, acc);
            acc = fmaf(d2, d2, acc);
            acc = fmaf(d3, d3, acc);
        }
        #pragma unroll
        for (int o = 16; o; o >>= 1) acc += __shfl_down_sync(0xffffffffu, acc, o);
        if (lane == 0) {
            float s = sqrtf(acc + 1e-12f);
            g_sraw[e] = s;
            atomicAdd(&g_deg[u], 1);
            sval = s;
        }
    }
    if (lane == 0) { smin[warp] = sval; smax[warp] = sval; }
    __syncthreads();
    if (threadIdx.x == 0) {
        float mn = smin[0], mx = smax[0];
        #pragma unroll
        for (int i = 1; i < 8; i++) { mn = fminf(mn, smin[i]); mx = fmaxf(mx, smax[i]); }
        atomicMin(&g_minb, __float_as_uint(mn));
        atomicMax(&g_maxb, __float_as_uint(mx));
    }
}

// exclusive scan of a fixed 4096-int array selected by `which`
__global__ void k_scan4096(int which) {
    const int* in; int* out;
    if (which == 0) { in = g_deg; out = g_rowptr; }
    else            { in = g_rn;  out = g_roff;   }
    __shared__ int sh[1024];
    int t = threadIdx.x;
    int v0 = in[t * 4 + 0], v1 = in[t * 4 + 1], v2 = in[t * 4 + 2], v3 = in[t * 4 + 3];
    int s = v0 + v1 + v2 + v3;
    sh[t] = s; __syncthreads();
    for (int off = 1; off < 1024; off <<= 1) {
        int a = (t >= off) ? sh[t - off] : 0;
        __syncthreads();
        sh[t] += a;
        __syncthreads();
    }
    int pre = t ? sh[t - 1] : 0;
    out[t * 4 + 0] = pre;
    out[t * 4 + 1] = pre + v0;
    out[t * 4 + 2] = pre + v0 + v1;
    out[t * 4 + 3] = pre + v0 + v1 + v2;
    if (t == 1023) out[4096] = sh[1023];
}

__global__ void k_norm_fill(const int* __restrict__ ei) {
    int e = blockIdx.x * 256 + threadIdx.x;
    float mn = __uint_as_float(g_minb), mx = __uint_as_float(g_maxb);
    float s = (g_sraw[e] - mn) / (mx - mn) + 0.5f;
    int u = ei[e], v = ei[N_EDGES + e];
    atomicAdd(&g_tot[u], s); atomicAdd(&g_tot[v], s);
    atomicAdd(&g_cntN[u], 1); atomicAdd(&g_cntN[v], 1);
    int slot = g_rowptr[u] + atomicAdd(&g_fill[u], 1);
    g_csr_key[slot] = ((unsigned long long)__float_as_uint(s) << 32) | (unsigned)e;
    g_csr_dst[slot] = v;
}

__global__ void k_avg() {
    int i = blockIdx.x * blockDim.x + threadIdx.x;
    if (i < N_NODES) g_avg[i] = g_tot[i] / (float)g_cntN[i];
}

// warp-per-seed Prim-style growth with per-row cached best candidates.
// A cached row-min only invalidates when its dst joins the cluster.
__global__ void __launch_bounds__(256) k_grow() {   // <<<512,256>>>
    int wid = threadIdx.x >> 5, lane = threadIdx.x & 31;
    int seed = blockIdx.x * 8 + wid;
    unsigned short joined[8];
    unsigned long long ck[8];
    int cd[8];
    #pragma unroll
    for (int j = 0; j < 8; j++) { joined[j] = 0xFFFF; ck[j] = ~0ull; cd[j] = -1; }
    joined[0] = (unsigned short)seed;
    int nj = 1; float tot = 0.f;

    // initial scan of seed row
    {
        unsigned long long bk = ~0ull; int bd = -1;
        int p0 = g_rowptr[seed], p1 = g_rowptr[seed + 1];
        for (int p = p0 + lane; p < p1; p += 32) {
            int d = g_csr_dst[p];
            bool in = false;
            #pragma unroll
            for (int j = 0; j < 8; j++) in |= (j < nj) && (joined[j] == (unsigned short)d);
            if (!in) {
                unsigned long long key = g_csr_key[p];
                if (key < bk) { bk = key; bd = d; }
            }
        }
        #pragma unroll
        for (int o = 16; o; o >>= 1) {
            unsigned long long ok = __shfl_down_sync(0xffffffffu, bk, o);
            int od = __shfl_down_sync(0xffffffffu, bd, o);
            if (ok < bk) { bk = ok; bd = od; }
        }
        bk = __shfl_sync(0xffffffffu, bk, 0);
        bd = __shfl_sync(0xffffffffu, bd, 0);
        ck[0] = bk; cd[0] = bd;
    }

    while (tot < 3.0f && nj < 8) {
        unsigned long long bk = ~0ull; int bd = -1;
        #pragma unroll
        for (int r = 0; r < 8; r++) if (r < nj && ck[r] < bk) { bk = ck[r]; bd = cd[r]; }
        if (bd < 0) break;
        tot += __uint_as_float((unsigned)(bk >> 32));
        joined[nj] = (unsigned short)bd;
        nj++;
        // rescan rows whose cached best just joined, and scan the new row
        #pragma unroll
        for (int r = 0; r < 8; r++) {
            if (r < nj && (cd[r] == bd || r == nj - 1)) {
                int u = joined[r];
                unsigned long long nk = ~0ull; int nd = -1;
                int p0 = g_rowptr[u], p1 = g_rowptr[u + 1];
                for (int p = p0 + lane; p < p1; p += 32) {
                    int d = g_csr_dst[p];
                    bool in = false;
                    #pragma unroll
                    for (int j = 0; j < 8; j++) in |= (j < nj) && (joined[j] == (unsigned short)d);
                    if (!in) {
                        unsigned long long key = g_csr_key[p];
                        if (key < nk) { nk = key; nd = d; }
                    }
                }
                #pragma unroll
                for (int o = 16; o; o >>= 1) {
                    unsigned long long ok = __shfl_down_sync(0xffffffffu, nk, o);
                    int od = __shfl_down_sync(0xffffffffu, nd, o);
                    if (ok < nk) { nk = ok; nd = od; }
                }
                nk = __shfl_sync(0xffffffffu, nk, 0);
                nd = __shfl_sync(0xffffffffu, nd, 0);
                ck[r] = nk; cd[r] = nd;
            }
        }
    }

    if (lane == 0) {
        // sort members ascending (0xFFFF sentinels to the end)
        unsigned short memb[8];
        #pragma unroll
        for (int j = 0; j < 8; j++) memb[j] = joined[j];
        #pragma unroll
        for (int a = 0; a < 7; a++)
            #pragma unroll
            for (int b = 0; b < 7 - a; b++) {
                unsigned short x0 = memb[b], x1 = memb[b + 1];
                memb[b] = (x0 < x1) ? x0 : x1;
                memb[b + 1] = (x0 < x1) ? x1 : x0;
            }
        #pragma unroll
        for (int j = 0; j < 8; j++) g_mem[seed][j] = memb[j];
        g_msz[seed] = nj;
        unsigned long long hi = 0, lo = 0;
        #pragma unroll
        for (int j = 0; j < 7; j++) {
            unsigned long long k = (j < nj) ? (unsigned long long)(8191u - memb[j]) : 0ull;
            if (j < 4) hi |= k << (48 - 16 * j);
            else       lo |= k << (48 - 16 * (j - 4));
        }
        g_khi[seed] = hi; g_klo[seed] = lo;   // lo bits [0:16) free
    }
}

// single-block bitonic sort of 4096 128-bit keys (idx packed in lo[0:16)),
// fused with adjacent-dedup + compaction + node->cluster CSR build.
__global__ void k_sort_dedup() {   // <<<1,1024, 65536>>>
    extern __shared__ unsigned long long sk[];   // [2*4096]
    __shared__ int sh[1024];
    int t = threadIdx.x;
    for (int r = t; r < N_NODES; r += 1024) {
        sk[2 * r] = g_khi[r];
        sk[2 * r + 1] = g_klo[r] | (unsigned long long)r;
    }
    __syncthreads();
    for (int k = 2; k <= N_NODES; k <<= 1) {
        for (int j = k >> 1; j > 0; j >>= 1) {
            for (int r = t; r < N_NODES; r += 1024) {
                int x = r ^ j;
                if (x > r) {
                    unsigned long long ah = sk[2 * r], al = sk[2 * r + 1];
                    unsigned long long bh = sk[2 * x], bl = sk[2 * x + 1];
                    bool agtb = (ah > bh) || (ah == bh && al > bl);
                    bool up = ((r & k) == 0);
                    if (agtb == up) {
                        sk[2 * r] = bh; sk[2 * r + 1] = bl;
                        sk[2 * x] = ah; sk[2 * x + 1] = al;
                    }
                }
            }
            __syncthreads();
        }
    }
    // dedup on (hi, lo & ~0xFFFF)
    int fl[4], loc[4];
    int s = 0;
    #pragma unroll
    for (int q = 0; q < 4; q++) {
        int r = t * 4 + q;
        int f;
        if (r == 0) f = 1;
        else {
            unsigned long long ph = sk[2 * (r - 1)], pl = sk[2 * (r - 1) + 1] & ~0xFFFFull;
            unsigned long long ch = sk[2 * r],       cl = sk[2 * r + 1] & ~0xFFFFull;
            f = (ph != ch) || (pl != cl);
        }
        fl[q] = f; loc[q] = s; s += f;
    }
    sh[t] = s; __syncthreads();
    for (int off = 1; off < 1024; off <<= 1) {
        int a = (t >= off) ? sh[t - off] : 0;
        __syncthreads();
        sh[t] += a;
        __syncthreads();
    }
    int pre = t ? sh[t - 1] : 0;
    #pragma unroll
    for (int q = 0; q < 4; q++) {
        int r = t * 4 + q;
        if (fl[q]) {
            int pos = pre + loc[q];
            int src = (int)(sk[2 * r + 1] & 0xFFFFull);
            #pragma unroll
            for (int j = 0; j < 8; j++) g_uniq[pos][j] = g_mem[src][j];
            g_usz[pos] = g_msz[src];
        }
    }
    if (t == 1023) g_U = sh[1023];
    __syncthreads();
    int U = g_U;
    // ---- fused node->cluster CSR build (reuse sk as int scratch) ----
    int* cnt = (int*)sk;               // [0..4096)
    int* ptr = ((int*)sk) + 4096;      // [4096..8193)
    int* fil = ((int*)sk) + 8200;      // [8200..12296)
    for (int i = t; i < N_NODES; i += 1024) cnt[i] = 0;
    __syncthreads();
    for (int u = t; u < U; u += 1024) {
        int sz = g_usz[u];
        for (int mi = 0; mi < sz; mi++) atomicAdd(&cnt[g_uniq[u][mi]], 1);
    }
    __syncthreads();
    {
        int v0 = cnt[t * 4 + 0], v1 = cnt[t * 4 + 1], v2 = cnt[t * 4 + 2], v3 = cnt[t * 4 + 3];
        int ss = v0 + v1 + v2 + v3;
        sh[t] = ss; __syncthreads();
        for (int off = 1; off < 1024; off <<= 1) {
            int a = (t >= off) ? sh[t - off] : 0;
            __syncthreads();
            sh[t] += a;
            __syncthreads();
        }
        int pr = t ? sh[t - 1] : 0;
        ptr[t * 4 + 0] = pr;
        ptr[t * 4 + 1] = pr + v0;
        ptr[t * 4 + 2] = pr + v0 + v1;
        ptr[t * 4 + 3] = pr + v0 + v1 + v2;
        if (t == 1023) ptr[4096] = sh[1023];
    }
    __syncthreads();
    for (int i = t; i <= N_NODES; i += 1024) g_n2uptr[i] = ptr[i];
    for (int i = t; i < N_NODES; i += 1024) fil[i] = 0;
    __syncthreads();
    for (int u = t; u < U; u += 1024) {
        int sz = g_usz[u];
        for (int mi = 0; mi < sz; mi++) {
            int m = g_uniq[u][mi];
            int slot = ptr[m] + atomicAdd(&fil[m], 1);
            g_n2ulist[slot] = u;
        }
    }
}

// ---------------- single-warp greedy max-cover: phase-descending exact sweep ----
// Counts only decrease => for phase k=7..1, an ascending index sweep selecting
// any cluster with cnt==k reproduces the exact (max count, smallest index)
// greedy order. No global argmax structure needed at all.
#define G_OFF_CNT   0         // u32[4096]
#define G_OFF_PTR   16384     // int[4097] (pad to 16400)
#define G_OFF_UQ    32784     // u16[4096*8]
#define G_OFF_SZ    98320     // u8[4096]
#define G_OFF_LS    102416    // u16[32768]
#define G_OFF_COV   167952    // u32[128]
#define G_OFF_BEG   168464    // int[8]
#define G_OFF_LEN   168496    // int[8]
#define G_SMEM_TOT  168528

__global__ void k_greedy() {   // <<<1,256, G_SMEM_TOT>>>
    extern __shared__ unsigned char sg[];
    unsigned* s_cnt      = (unsigned*)(sg + G_OFF_CNT);
    int* s_ptr           = (int*)(sg + G_OFF_PTR);
    unsigned short* s_uq = (unsigned short*)(sg + G_OFF_UQ);
    unsigned char* s_sz  = (unsigned char*)(sg + G_OFF_SZ);
    unsigned short* s_ls = (unsigned short*)(sg + G_OFF_LS);
    unsigned* s_cov      = (unsigned*)(sg + G_OFF_COV);
    int* s_beg           = (int*)(sg + G_OFF_BEG);
    int* s_len           = (int*)(sg + G_OFF_LEN);

    int t = threadIdx.x;
    int U = g_U;
    int T = g_n2uptr[N_NODES];

    for (int i = t; i < 128; i += 256) s_cov[i] = 0;
    for (int c = t; c < N_NODES; c += 256) {
        int cc = (c < U) ? g_usz[c] : 0;
        s_cnt[c] = (unsigned)cc;
        s_sz[c] = (unsigned char)cc;
        ((uint4*)s_uq)[c] = ((const uint4*)g_uniq)[c];
    }
    for (int i = t; i <= N_NODES; i += 256) s_ptr[i] = g_n2uptr[i];
    for (int i = t; i < T; i += 256) s_ls[i] = (unsigned short)g_n2ulist[i];
    __syncthreads();
    if (t >= 32) return;

    int lane = t;
    int covered = 0, K = 0;
    for (int phase = 7; phase >= 1 && covered < N_NODES; phase--) {
        for (int base = 0; base < N_NODES && covered < N_NODES; base += 32) {
            int start = 0;
            while (covered < N_NODES) {
                unsigned cc = s_cnt[base + lane];
                unsigned mask = __ballot_sync(0xffffffffu,
                                              (lane >= start) && ((int)cc == phase));
                if (!mask) break;
                int i = __ffs(mask) - 1;
                int c = base + i;
                if (lane == 0) g_sel[K & (N_NODES - 1)] = c;
                K++;
                // ---- mark newly covered members (sz <= 7, lane-parallel) ----
                int sz = s_sz[c];
                int m = (lane < sz) ? (int)s_uq[c * 8 + lane] : -1;
                bool isnew = false;
                if (m >= 0) {
                    unsigned w = s_cov[m >> 5];
                    isnew = !((w >> (m & 31)) & 1u);
                }
                if (isnew) atomicOr(&s_cov[m >> 5], 1u << (m & 31));
                unsigned nb = __ballot_sync(0xffffffffu, isnew);
                int newcnt = __popc(nb);
                covered += newcnt;
                if (isnew) {
                    int slot = __popc(nb & ((1u << lane) - 1));
                    int b0 = s_ptr[m];
                    s_beg[slot] = b0;
                    s_len[slot] = s_ptr[m + 1] - b0;
                }
                __syncwarp();
                // register prefix of up to 7 lengths
                int offk[7]; int tot = 0;
                #pragma unroll
                for (int kk = 0; kk < 7; kk++) { offk[kk] = tot; if (kk < newcnt) tot += s_len[kk]; }
                // ---- exact decrements ----
                for (int p = lane; p < tot; p += 32) {
                    int kk = 0;
                    #pragma unroll
                    for (int q = 1; q < 7; q++) if (q < newcnt && p >= offk[q]) kk = q;
                    int c2 = (int)s_ls[s_beg[kk] + (p - offk[kk])];
                    atomicSub(&s_cnt[c2], 1u);
                }
                __syncwarp();
                start = i;   // c itself dropped to 0; counts ahead may have changed -> reload
            }
        }
    }
    if (lane == 0) g_K = K;
}

// fused c2 count + scan + fill (single block)
__global__ void k_c2() {   // <<<1,1024, 49184>>>
    extern __shared__ int sc[];
    int* cnt = sc;            // [0..4096)
    int* ptr = sc + 4096;     // [4096..8193)
    int* fil = sc + 8200;     // [8200..12296)
    __shared__ int sh[1024];
    int t = threadIdx.x;
    int K = g_K;
    for (int i = t; i < N_NODES; i += 1024) cnt[i] = 0;
    __syncthreads();
    for (int k = t; k < K; k += 1024) {
        int c = g_sel[k];
        int sz = g_usz[c];
        for (int mi = 0; mi < sz; mi++) atomicAdd(&cnt[g_uniq[c][mi]], 1);
    }
    __syncthreads();
    {
        int v0 = cnt[t * 4 + 0], v1 = cnt[t * 4 + 1], v2 = cnt[t * 4 + 2], v3 = cnt[t * 4 + 3];
        int ss = v0 + v1 + v2 + v3;
        sh[t] = ss; __syncthreads();
        for (int off = 1; off < 1024; off <<= 1) {
            int a = (t >= off) ? sh[t - off] : 0;
            __syncthreads();
            sh[t] += a;
            __syncthreads();
        }
        int pr = t ? sh[t - 1] : 0;
        ptr[t * 4 + 0] = pr;
        ptr[t * 4 + 1] = pr + v0;
        ptr[t * 4 + 2] = pr + v0 + v1;
        ptr[t * 4 + 3] = pr + v0 + v1 + v2;
        if (t == 1023) ptr[4096] = sh[1023];
    }
    __syncthreads();
    for (int i = t; i <= N_NODES; i += 1024) g_c2ptr[i] = ptr[i];
    for (int i = t; i < N_NODES; i += 1024) fil[i] = 0;
    __syncthreads();
    for (int k = t; k < K; k += 1024) {
        int c = g_sel[k];
        int sz = g_usz[c];
        for (int mi = 0; mi < sz; mi++) {
            int m = g_uniq[c][mi];
            int slot = ptr[m] + atomicAdd(&fil[m], 1);
            g_c2list[slot] = k;
        }
    }
}

__global__ void k_clearB() {
    int tot16 = (g_K * N_NODES) >> 4;
    int stride = gridDim.x * blockDim.x;
    uint4 z = make_uint4(0, 0, 0, 0);
    uint4* B4 = (uint4*)g_B;
    for (int i = blockIdx.x * blockDim.x + threadIdx.x; i < tot16; i += stride)
        B4[i] = z;
}

__global__ void k_markB(const int* __restrict__ ei) {
    int e = blockIdx.x * 256 + threadIdx.x;
    int u = ei[e], v = ei[N_EDGES + e];
    int a0 = g_c2ptr[u], a1 = g_c2ptr[u + 1];
    int b0 = g_c2ptr[v], b1 = g_c2ptr[v + 1];
    for (int p = a0; p < a1; p++) {
        size_t base = (size_t)g_c2list[p] * N_NODES;
        for (int q = b0; q < b1; q++) g_B[base + g_c2list[q]] = 1;
    }
}

// warp-per-row popcount of adjacency rows (limited to K cols)
__global__ void k_rowcnt() {   // <<<512,256>>>
    int gw = (blockIdx.x * blockDim.x + threadIdx.x) >> 5;
    int lane = threadIdx.x & 31;
    if (gw >= N_NODES) return;
    int K = g_K;
    if (gw >= K) { if (lane == 0) g_rn[gw] = 0; return; }
    const unsigned* row = (const unsigned*)(g_B + (size_t)gw * N_NODES);
    int words = (K + 3) >> 2;
    int c = 0;
    for (int j = lane; j < words; j += 32) c += __popc(row[j]);
    #pragma unroll
    for (int o = 16; o; o >>= 1) c += __shfl_down_sync(0xffffffffu, c, o);
    if (lane == 0) g_rn[gw] = c - (int)g_B[(size_t)gw * N_NODES + gw];
}

// warp-per-row ballot compaction into the edge list
__global__ void k_write_edges(float* __restrict__ out) {   // <<<512,256>>>
    int gw = (blockIdx.x * blockDim.x + threadIdx.x) >> 5;
    int lane = threadIdx.x & 31;
    if (gw >= N_NODES) return;
    int K = g_K;
    if (gw >= K) return;
    int nnz = g_roff[K];
    const unsigned char* row = g_B + (size_t)gw * N_NODES;
    int p = g_roff[gw];
    for (int base = 0; base < K; base += 32) {
        int j = base + lane;
        bool v = (j < K) && (j != gw) && (row[j] != 0);
        unsigned m = __ballot_sync(0xffffffffu, v);
        if (v) {
            int off = __popc(m & ((1u << lane) - 1));
            out[p + off] = (float)gw;
            out[nnz + p + off] = (float)j;
        }
        p += __popc(m);
    }
}

// fused outputs: S rows, Ms rows, x_new, edge_index copy
__global__ void k_outputs(const float* __restrict__ x, const int* __restrict__ ei,
                          float* __restrict__ out) {   // <<<8704,256>>>
    int b = blockIdx.x, t = threadIdx.x;
    int K = g_K;
    int nnz = g_roff[K];
    size_t offX = 2 * (size_t)nnz;
    size_t offS = offX + (size_t)K * D_FEAT;
    size_t offM = offS + (size_t)K * N_NODES;
    size_t offE = offM + (size_t)K * N_NODES;
    if (b < 4096) {
        if (b >= K) return;
        int c = g_sel[b];
        int sz = g_usz[c];
        unsigned short mb[8];
        #pragma unroll
        for (int j = 0; j < 8; j++) mb[j] = (j < sz) ? g_uniq[c][j] : 0xFFFF;
        size_t baseS = offS + (size_t)b * N_NODES;
        size_t baseM = offM + (size_t)b * N_NODES;
        for (int j = t; j < N_NODES; j += 256) {
            bool in = false;
            #pragma unroll
            for (int q = 0; q < 8; q++) in |= (mb[q] == (unsigned short)j);
            float mv = in ? g_avg[j] : 0.f;
            out[baseS + j] = in ? 1.f : 0.f;
            out[baseM + j] = mv;
        }
    } else if (b < 8192) {
        int k = b - 4096;
        if (k >= K) return;
        int c = g_sel[k];
        int sz = g_usz[c];
        float acc = 0.f;
        for (int mi = 0; mi < sz; mi++) {
            int m = g_uniq[c][mi];
            acc += g_avg[m] * x[(size_t)m * D_FEAT + t];
        }
        out[offX + (size_t)k * D_FEAT + t] = acc;
    } else {
        int i = (b - 8192) * 256 + t;
        out[offE + i] = (float)ei[i];
    }
}

// ------------------------- launch -------------------------
extern "C" void kernel_launch(void* const* d_in, const int* in_sizes, int n_in,
                              void* d_out, int out_size) {
    const float* x  = (const float*)d_in[0];
    const int*   ei = (const int*)d_in[1];
    float*       out = (float*)d_out;
    cudaStream_t st = cudaStreamPerThread;

    cudaFuncSetAttribute(k_sort_dedup, cudaFuncAttributeMaxDynamicSharedMemorySize, 65536);
    cudaFuncSetAttribute(k_greedy, cudaFuncAttributeMaxDynamicSharedMemorySize, G_SMEM_TOT);
    cudaFuncSetAttribute(k_c2, cudaFuncAttributeMaxDynamicSharedMemorySize, 49184);

    k_init       <<<16, 256, 0, st>>>();
    k_dist       <<<N_EDGES / 8, 256, 0, st>>>(x, ei);
    k_scan4096   <<<1, 1024, 0, st>>>(0);            // deg -> rowptr
    k_norm_fill  <<<N_EDGES / 256, 256, 0, st>>>(ei);
    k_avg        <<<16, 256, 0, st>>>();
    k_grow       <<<512, 256, 0, st>>>();
    k_sort_dedup <<<1, 1024, 65536, st>>>();
    k_greedy     <<<1, 256, G_SMEM_TOT, st>>>();
    k_c2         <<<1, 1024, 49184, st>>>();
    k_clearB     <<<512, 256, 0, st>>>();
    k_markB      <<<N_EDGES / 256, 256, 0, st>>>(ei);
    k_rowcnt     <<<512, 256, 0, st>>>();
    k_scan4096   <<<1, 1024, 0, st>>>(1);            // rn -> roff
    k_write_edges<<<512, 256, 0, st>>>(out);
    k_outputs    <<<8704, 256, 0, st>>>(x, ei, out);
}

// round 10
// speedup vs baseline: 4.5165x; 1.0703x over previous
#include <cuda_runtime.h>
#include <cstdint>

#define N_NODES 4096
#define D_FEAT  256
#define N_EDGES 65536

// ------------------------- static device scratch -------------------------
static __device__ float g_sraw[N_EDGES];
static __device__ unsigned g_minb, g_maxb;
static __device__ int   g_deg[N_NODES];
static __device__ int   g_rowptr[N_NODES + 1];
static __device__ int   g_fill[N_NODES];
static __device__ unsigned long long g_csr_key[N_EDGES];   // (score_bits<<32)|eid
static __device__ int   g_csr_dst[N_EDGES];
static __device__ float g_tot[N_NODES];
static __device__ int   g_cntN[N_NODES];
static __device__ float g_avg[N_NODES];
static __device__ __align__(16) unsigned short g_mem[N_NODES][8];
static __device__ int   g_msz[N_NODES];
static __device__ unsigned long long g_khi[N_NODES], g_klo[N_NODES];
static __device__ __align__(16) unsigned short g_uniq[N_NODES][8];
static __device__ int   g_usz[N_NODES];
static __device__ int   g_U;
static __device__ int   g_n2uptr[N_NODES + 1];
static __device__ int   g_n2ulist[N_NODES * 8];
static __device__ int   g_sel[N_NODES];
static __device__ int   g_K;
static __device__ int   g_c2ptr[N_NODES + 1];
static __device__ int   g_c2list[N_NODES * 8];
static __device__ unsigned char g_B[(size_t)N_NODES * N_NODES];   // cluster adj bitmap
static __device__ int   g_rn[N_NODES], g_roff[N_NODES + 1];

// ------------------------- kernels -------------------------

__global__ void k_init() {
    int i = blockIdx.x * blockDim.x + threadIdx.x;
    if (i < N_NODES) {
        g_deg[i] = 0; g_fill[i] = 0;
        g_tot[i] = 0.f; g_cntN[i] = 0;
    }
    if (i == 0) { g_minb = 0x7f800000u; g_maxb = 0u; }
}

// one warp per edge: fp32 distance (float4 loads), degree count, global min/max
__global__ void k_dist(const float* __restrict__ x, const int* __restrict__ ei) {
    int warp = threadIdx.x >> 5, lane = threadIdx.x & 31;
    int e = blockIdx.x * 8 + warp;
    __shared__ float smin[8], smax[8];
    float sval = __int_as_float(0x7f800000);
    {
        int u = ei[e], v = ei[N_EDGES + e];
        const float4* xu = (const float4*)(x + (size_t)u * D_FEAT);
        const float4* xv = (const float4*)(x + (size_t)v * D_FEAT);
        float acc = 0.f;
        #pragma unroll
        for (int i = 0; i < 2; i++) {
            float4 a = xu[lane + 32 * i], b = xv[lane + 32 * i];
            float d0 = a.x - b.x, d1 = a.y - b.y, d2 = a.z - b.z, d3 = a.w - b.w;
            acc = fmaf(d0, d0, acc);
            acc = fmaf(d1, d1, acc);
            acc = fmaf(d2, d2, acc);
            acc = fmaf(d3, d3, acc);
        }
        #pragma unroll
        for (int o = 16; o; o >>= 1) acc += __shfl_down_sync(0xffffffffu, acc, o);
        if (lane == 0) {
            float s = sqrtf(acc + 1e-12f);
            g_sraw[e] = s;
            atomicAdd(&g_deg[u], 1);
            sval = s;
        }
    }
    if (lane == 0) { smin[warp] = sval; smax[warp] = sval; }
    __syncthreads();
    if (threadIdx.x == 0) {
        float mn = smin[0], mx = smax[0];
        #pragma unroll
        for (int i = 1; i < 8; i++) { mn = fminf(mn, smin[i]); mx = fmaxf(mx, smax[i]); }
        atomicMin(&g_minb, __float_as_uint(mn));
        atomicMax(&g_maxb, __float_as_uint(mx));
    }
}

// exclusive scan of a fixed 4096-int array selected by `which`
__global__ void k_scan4096(int which) {
    const int* in; int* out;
    if (which == 0) { in = g_deg; out = g_rowptr; }
    else            { in = g_rn;  out = g_roff;   }
    __shared__ int sh[1024];
    int t = threadIdx.x;
    int v0 = in[t * 4 + 0], v1 = in[t * 4 + 1], v2 = in[t * 4 + 2], v3 = in[t * 4 + 3];
    int s = v0 + v1 + v2 + v3;
    sh[t] = s; __syncthreads();
    for (int off = 1; off < 1024; off <<= 1) {
        int a = (t >= off) ? sh[t - off] : 0;
        __syncthreads();
        sh[t] += a;
        __syncthreads();
    }
    int pre = t ? sh[t - 1] : 0;
    out[t * 4 + 0] = pre;
    out[t * 4 + 1] = pre + v0;
    out[t * 4 + 2] = pre + v0 + v1;
    out[t * 4 + 3] = pre + v0 + v1 + v2;
    if (t == 1023) out[4096] = sh[1023];
}

__global__ void k_norm_fill(const int* __restrict__ ei) {
    int e = blockIdx.x * 256 + threadIdx.x;
    float mn = __uint_as_float(g_minb), mx = __uint_as_float(g_maxb);
    float s = (g_sraw[e] - mn) / (mx - mn) + 0.5f;
    int u = ei[e], v = ei[N_EDGES + e];
    atomicAdd(&g_tot[u], s); atomicAdd(&g_tot[v], s);
    atomicAdd(&g_cntN[u], 1); atomicAdd(&g_cntN[v], 1);
    int slot = g_rowptr[u] + atomicAdd(&g_fill[u], 1);
    g_csr_key[slot] = ((unsigned long long)__float_as_uint(s) << 32) | (unsigned)e;
    g_csr_dst[slot] = v;
}

__global__ void k_avg() {
    int i = blockIdx.x * blockDim.x + threadIdx.x;
    if (i < N_NODES) g_avg[i] = g_tot[i] / (float)g_cntN[i];
}

// warp-per-seed Prim-style growth with per-row cached best candidates.
// A cached row-min only invalidates when its dst joins the cluster.
__global__ void __launch_bounds__(256) k_grow() {   // <<<512,256>>>
    int wid = threadIdx.x >> 5, lane = threadIdx.x & 31;
    int seed = blockIdx.x * 8 + wid;
    unsigned short joined[8];
    unsigned long long ck[8];
    int cd[8];
    #pragma unroll
    for (int j = 0; j < 8; j++) { joined[j] = 0xFFFF; ck[j] = ~0ull; cd[j] = -1; }
    joined[0] = (unsigned short)seed;
    int nj = 1; float tot = 0.f;

    // initial scan of seed row
    {
        unsigned long long bk = ~0ull; int bd = -1;
        int p0 = g_rowptr[seed], p1 = g_rowptr[seed + 1];
        for (int p = p0 + lane; p < p1; p += 32) {
            int d = g_csr_dst[p];
            bool in = false;
            #pragma unroll
            for (int j = 0; j < 8; j++) in |= (j < nj) && (joined[j] == (unsigned short)d);
            if (!in) {
                unsigned long long key = g_csr_key[p];
                if (key < bk) { bk = key; bd = d; }
            }
        }
        #pragma unroll
        for (int o = 16; o; o >>= 1) {
            unsigned long long ok = __shfl_down_sync(0xffffffffu, bk, o);
            int od = __shfl_down_sync(0xffffffffu, bd, o);
            if (ok < bk) { bk = ok; bd = od; }
        }
        bk = __shfl_sync(0xffffffffu, bk, 0);
        bd = __shfl_sync(0xffffffffu, bd, 0);
        ck[0] = bk; cd[0] = bd;
    }

    while (tot < 3.0f && nj < 8) {
        unsigned long long bk = ~0ull; int bd = -1;
        #pragma unroll
        for (int r = 0; r < 8; r++) if (r < nj && ck[r] < bk) { bk = ck[r]; bd = cd[r]; }
        if (bd < 0) break;
        tot += __uint_as_float((unsigned)(bk >> 32));
        joined[nj] = (unsigned short)bd;
        nj++;
        // rescan rows whose cached best just joined, and scan the new row
        #pragma unroll
        for (int r = 0; r < 8; r++) {
            if (r < nj && (cd[r] == bd || r == nj - 1)) {
                int u = joined[r];
                unsigned long long nk = ~0ull; int nd = -1;
                int p0 = g_rowptr[u], p1 = g_rowptr[u + 1];
                for (int p = p0 + lane; p < p1; p += 32) {
                    int d = g_csr_dst[p];
                    bool in = false;
                    #pragma unroll
                    for (int j = 0; j < 8; j++) in |= (j < nj) && (joined[j] == (unsigned short)d);
                    if (!in) {
                        unsigned long long key = g_csr_key[p];
                        if (key < nk) { nk = key; nd = d; }
                    }
                }
                #pragma unroll
                for (int o = 16; o; o >>= 1) {
                    unsigned long long ok = __shfl_down_sync(0xffffffffu, nk, o);
                    int od = __shfl_down_sync(0xffffffffu, nd, o);
                    if (ok < nk) { nk = ok; nd = od; }
                }
                nk = __shfl_sync(0xffffffffu, nk, 0);
                nd = __shfl_sync(0xffffffffu, nd, 0);
                ck[r] = nk; cd[r] = nd;
            }
        }
    }

    if (lane == 0) {
        // sort members ascending (0xFFFF sentinels to the end)
        unsigned short memb[8];
        #pragma unroll
        for (int j = 0; j < 8; j++) memb[j] = joined[j];
        #pragma unroll
        for (int a = 0; a < 7; a++)
            #pragma unroll
            for (int b = 0; b < 7 - a; b++) {
                unsigned short x0 = memb[b], x1 = memb[b + 1];
                memb[b] = (x0 < x1) ? x0 : x1;
                memb[b + 1] = (x0 < x1) ? x1 : x0;
            }
        #pragma unroll
        for (int j = 0; j < 8; j++) g_mem[seed][j] = memb[j];
        g_msz[seed] = nj;
        unsigned long long hi = 0, lo = 0;
        #pragma unroll
        for (int j = 0; j < 7; j++) {
            unsigned long long k = (j < nj) ? (unsigned long long)(8191u - memb[j]) : 0ull;
            if (j < 4) hi |= k << (48 - 16 * j);
            else       lo |= k << (48 - 16 * (j - 4));
        }
        g_khi[seed] = hi; g_klo[seed] = lo;   // lo bits [0:16) free
    }
}

// single-block bitonic sort of 4096 128-bit keys (idx packed in lo[0:16)),
// fused with adjacent-dedup + compaction + node->cluster CSR build.
__global__ void k_sort_dedup() {   // <<<1,1024, 65536>>>
    extern __shared__ unsigned long long sk[];   // [2*4096]
    __shared__ int sh[1024];
    int t = threadIdx.x;
    for (int r = t; r < N_NODES; r += 1024) {
        sk[2 * r] = g_khi[r];
        sk[2 * r + 1] = g_klo[r] | (unsigned long long)r;
    }
    __syncthreads();
    for (int k = 2; k <= N_NODES; k <<= 1) {
        for (int j = k >> 1; j > 0; j >>= 1) {
            for (int r = t; r < N_NODES; r += 1024) {
                int x = r ^ j;
                if (x > r) {
                    unsigned long long ah = sk[2 * r], al = sk[2 * r + 1];
                    unsigned long long bh = sk[2 * x], bl = sk[2 * x + 1];
                    bool agtb = (ah > bh) || (ah == bh && al > bl);
                    bool up = ((r & k) == 0);
                    if (agtb == up) {
                        sk[2 * r] = bh; sk[2 * r + 1] = bl;
                        sk[2 * x] = ah; sk[2 * x + 1] = al;
                    }
                }
            }
            __syncthreads();
        }
    }
    // dedup on (hi, lo & ~0xFFFF)
    int fl[4], loc[4];
    int s = 0;
    #pragma unroll
    for (int q = 0; q < 4; q++) {
        int r = t * 4 + q;
        int f;
        if (r == 0) f = 1;
        else {
            unsigned long long ph = sk[2 * (r - 1)], pl = sk[2 * (r - 1) + 1] & ~0xFFFFull;
            unsigned long long ch = sk[2 * r],       cl = sk[2 * r + 1] & ~0xFFFFull;
            f = (ph != ch) || (pl != cl);
        }
        fl[q] = f; loc[q] = s; s += f;
    }
    sh[t] = s; __syncthreads();
    for (int off = 1; off < 1024; off <<= 1) {
        int a = (t >= off) ? sh[t - off] : 0;
        __syncthreads();
        sh[t] += a;
        __syncthreads();
    }
    int pre = t ? sh[t - 1] : 0;
    #pragma unroll
    for (int q = 0; q < 4; q++) {
        int r = t * 4 + q;
        if (fl[q]) {
            int pos = pre + loc[q];
            int src = (int)(sk[2 * r + 1] & 0xFFFFull);
            #pragma unroll
            for (int j = 0; j < 8; j++) g_uniq[pos][j] = g_mem[src][j];
            g_usz[pos] = g_msz[src];
        }
    }
    if (t == 1023) g_U = sh[1023];
    __syncthreads();
    int U = g_U;
    // ---- fused node->cluster CSR build (reuse sk as int scratch) ----
    int* cnt = (int*)sk;               // [0..4096)
    int* ptr = ((int*)sk) + 4096;      // [4096..8193)
    int* fil = ((int*)sk) + 8200;      // [8200..12296)
    for (int i = t; i < N_NODES; i += 1024) cnt[i] = 0;
    __syncthreads();
    for (int u = t; u < U; u += 1024) {
        int sz = g_usz[u];
        for (int mi = 0; mi < sz; mi++) atomicAdd(&cnt[g_uniq[u][mi]], 1);
    }
    __syncthreads();
    {
        int v0 = cnt[t * 4 + 0], v1 = cnt[t * 4 + 1], v2 = cnt[t * 4 + 2], v3 = cnt[t * 4 + 3];
        int ss = v0 + v1 + v2 + v3;
        sh[t] = ss; __syncthreads();
        for (int off = 1; off < 1024; off <<= 1) {
            int a = (t >= off) ? sh[t - off] : 0;
            __syncthreads();
            sh[t] += a;
            __syncthreads();
        }
        int pr = t ? sh[t - 1] : 0;
        ptr[t * 4 + 0] = pr;
        ptr[t * 4 + 1] = pr + v0;
        ptr[t * 4 + 2] = pr + v0 + v1;
        ptr[t * 4 + 3] = pr + v0 + v1 + v2;
        if (t == 1023) ptr[4096] = sh[1023];
    }
    __syncthreads();
    for (int i = t; i <= N_NODES; i += 1024) g_n2uptr[i] = ptr[i];
    for (int i = t; i < N_NODES; i += 1024) fil[i] = 0;
    __syncthreads();
    for (int u = t; u < U; u += 1024) {
        int sz = g_usz[u];
        for (int mi = 0; mi < sz; mi++) {
            int m = g_uniq[u][mi];
            int slot = ptr[m] + atomicAdd(&fil[m], 1);
            g_n2ulist[slot] = u;
        }
    }
}

// ---------------- single-warp greedy max-cover: phase-descending exact sweep ----
// Counts only decrease => for phase k=7..1, an ascending index sweep selecting
// any cluster with cnt==k reproduces the exact (max count, smallest index)
// greedy order. Per-lane serial decrements (no flatten/prefix machinery).
#define G_OFF_CNT   0         // u32[4096]
#define G_OFF_PTR   16384     // int[4097] (pad to 16400)
#define G_OFF_UQ    32784     // u16[4096*8]
#define G_OFF_SZ    98320     // u8[4096]
#define G_OFF_LS    102416    // u16[32768]
#define G_OFF_COV   167952    // u32[128]
#define G_SMEM_TOT  168464

__global__ void k_greedy() {   // <<<1,256, G_SMEM_TOT>>>
    extern __shared__ unsigned char sg[];
    unsigned* s_cnt      = (unsigned*)(sg + G_OFF_CNT);
    int* s_ptr           = (int*)(sg + G_OFF_PTR);
    unsigned short* s_uq = (unsigned short*)(sg + G_OFF_UQ);
    unsigned char* s_sz  = (unsigned char*)(sg + G_OFF_SZ);
    unsigned short* s_ls = (unsigned short*)(sg + G_OFF_LS);
    unsigned* s_cov      = (unsigned*)(sg + G_OFF_COV);

    int t = threadIdx.x;
    int U = g_U;
    int T = g_n2uptr[N_NODES];

    for (int i = t; i < 128; i += 256) s_cov[i] = 0;
    for (int c = t; c < N_NODES; c += 256) {
        int cc = (c < U) ? g_usz[c] : 0;
        s_cnt[c] = (unsigned)cc;
        s_sz[c] = (unsigned char)cc;
        ((uint4*)s_uq)[c] = ((const uint4*)g_uniq)[c];
    }
    for (int i = t; i <= N_NODES; i += 256) s_ptr[i] = g_n2uptr[i];
    for (int i = t; i < T; i += 256) s_ls[i] = (unsigned short)g_n2ulist[i];
    __syncthreads();
    if (t >= 32) return;

    int lane = t;
    int covered = 0, K = 0;
    for (int phase = 7; phase >= 1 && covered < N_NODES; phase--) {
        for (int base = 0; base < N_NODES && covered < N_NODES; base += 32) {
            int start = 0;
            while (covered < N_NODES) {
                unsigned cc = s_cnt[base + lane];
                unsigned mask = __ballot_sync(0xffffffffu,
                                              (lane >= start) && ((int)cc == phase));
                if (!mask) break;
                int i = __ffs(mask) - 1;
                int c = base + i;
                if (lane == 0) g_sel[K & (N_NODES - 1)] = c;
                K++;
                // ---- mark newly covered members (sz <= 7, lane-parallel) ----
                int sz = s_sz[c];
                int m = (lane < sz) ? (int)s_uq[c * 8 + lane] : -1;
                bool isnew = false;
                if (m >= 0) {
                    unsigned w = s_cov[m >> 5];
                    isnew = !((w >> (m & 31)) & 1u);
                }
                if (isnew) atomicOr(&s_cov[m >> 5], 1u << (m & 31));
                unsigned nb = __ballot_sync(0xffffffffu, isnew);
                covered += __popc(nb);
                // ---- per-lane serial decrements over this node's cluster list ----
                if (isnew) {
                    int p0 = s_ptr[m], p1 = s_ptr[m + 1];
                    for (int p = p0; p < p1; p++)
                        atomicSub(&s_cnt[(int)s_ls[p]], 1u);
                }
                __syncwarp();
                start = i;   // c itself dropped to 0; counts ahead may have changed -> reload
            }
        }
    }
    if (lane == 0) g_K = K;
}

// fused c2 count + scan + fill (single block)
__global__ void k_c2() {   // <<<1,1024, 49184>>>
    extern __shared__ int sc[];
    int* cnt = sc;            // [0..4096)
    int* ptr = sc + 4096;     // [4096..8193)
    int* fil = sc + 8200;     // [8200..12296)
    __shared__ int sh[1024];
    int t = threadIdx.x;
    int K = g_K;
    for (int i = t; i < N_NODES; i += 1024) cnt[i] = 0;
    __syncthreads();
    for (int k = t; k < K; k += 1024) {
        int c = g_sel[k];
        int sz = g_usz[c];
        for (int mi = 0; mi < sz; mi++) atomicAdd(&cnt[g_uniq[c][mi]], 1);
    }
    __syncthreads();
    {
        int v0 = cnt[t * 4 + 0], v1 = cnt[t * 4 + 1], v2 = cnt[t * 4 + 2], v3 = cnt[t * 4 + 3];
        int ss = v0 + v1 + v2 + v3;
        sh[t] = ss; __syncthreads();
        for (int off = 1; off < 1024; off <<= 1) {
            int a = (t >= off) ? sh[t - off] : 0;
            __syncthreads();
            sh[t] += a;
            __syncthreads();
        }
        int pr = t ? sh[t - 1] : 0;
        ptr[t * 4 + 0] = pr;
        ptr[t * 4 + 1] = pr + v0;
        ptr[t * 4 + 2] = pr + v0 + v1;
        ptr[t * 4 + 3] = pr + v0 + v1 + v2;
        if (t == 1023) ptr[4096] = sh[1023];
    }
    __syncthreads();
    for (int i = t; i <= N_NODES; i += 1024) g_c2ptr[i] = ptr[i];
    for (int i = t; i < N_NODES; i += 1024) fil[i] = 0;
    __syncthreads();
    for (int k = t; k < K; k += 1024) {
        int c = g_sel[k];
        int sz = g_usz[c];
        for (int mi = 0; mi < sz; mi++) {
            int m = g_uniq[c][mi];
            int slot = ptr[m] + atomicAdd(&fil[m], 1);
            g_c2list[slot] = k;
        }
    }
}

__global__ void k_clearB() {
    int tot16 = (g_K * N_NODES) >> 4;
    int stride = gridDim.x * blockDim.x;
    uint4 z = make_uint4(0, 0, 0, 0);
    uint4* B4 = (uint4*)g_B;
    for (int i = blockIdx.x * blockDim.x + threadIdx.x; i < tot16; i += stride)
        B4[i] = z;
}

__global__ void k_markB(const int* __restrict__ ei) {
    int e = blockIdx.x * 256 + threadIdx.x;
    int u = ei[e], v = ei[N_EDGES + e];
    int a0 = g_c2ptr[u], a1 = g_c2ptr[u + 1];
    int b0 = g_c2ptr[v], b1 = g_c2ptr[v + 1];
    for (int p = a0; p < a1; p++) {
        size_t base = (size_t)g_c2list[p] * N_NODES;
        for (int q = b0; q < b1; q++) g_B[base + g_c2list[q]] = 1;
    }
}

// warp-per-row popcount of adjacency rows (limited to K cols)
__global__ void k_rowcnt() {   // <<<512,256>>>
    int gw = (blockIdx.x * blockDim.x + threadIdx.x) >> 5;
    int lane = threadIdx.x & 31;
    if (gw >= N_NODES) return;
    int K = g_K;
    if (gw >= K) { if (lane == 0) g_rn[gw] = 0; return; }
    const unsigned* row = (const unsigned*)(g_B + (size_t)gw * N_NODES);
    int words = (K + 3) >> 2;
    int c = 0;
    for (int j = lane; j < words; j += 32) c += __popc(row[j]);
    #pragma unroll
    for (int o = 16; o; o >>= 1) c += __shfl_down_sync(0xffffffffu, c, o);
    if (lane == 0) g_rn[gw] = c - (int)g_B[(size_t)gw * N_NODES + gw];
}

// warp-per-row ballot compaction into the edge list
__global__ void k_write_edges(float* __restrict__ out) {   // <<<512,256>>>
    int gw = (blockIdx.x * blockDim.x + threadIdx.x) >> 5;
    int lane = threadIdx.x & 31;
    if (gw >= N_NODES) return;
    int K = g_K;
    if (gw >= K) return;
    int nnz = g_roff[K];
    const unsigned char* row = g_B + (size_t)gw * N_NODES;
    int p = g_roff[gw];
    for (int base = 0; base < K; base += 32) {
        int j = base + lane;
        bool v = (j < K) && (j != gw) && (row[j] != 0);
        unsigned m = __ballot_sync(0xffffffffu, v);
        if (v) {
            int off = __popc(m & ((1u << lane) - 1));
            out[p + off] = (float)gw;
            out[nnz + p + off] = (float)j;
        }
        p += __popc(m);
    }
}

// fused outputs: S rows, Ms rows, x_new, edge_index copy
__global__ void k_outputs(const float* __restrict__ x, const int* __restrict__ ei,
                          float* __restrict__ out) {   // <<<8704,256>>>
    int b = blockIdx.x, t = threadIdx.x;
    int K = g_K;
    int nnz = g_roff[K];
    size_t offX = 2 * (size_t)nnz;
    size_t offS = offX + (size_t)K * D_FEAT;
    size_t offM = offS + (size_t)K * N_NODES;
    size_t offE = offM + (size_t)K * N_NODES;
    if (b < 4096) {
        if (b >= K) return;
        int c = g_sel[b];
        int sz = g_usz[c];
        unsigned short mb[8];
        #pragma unroll
        for (int j = 0; j < 8; j++) mb[j] = (j < sz) ? g_uniq[c][j] : 0xFFFF;
        size_t baseS = offS + (size_t)b * N_NODES;
        size_t baseM = offM + (size_t)b * N_NODES;
        for (int j = t; j < N_NODES; j += 256) {
            bool in = false;
            #pragma unroll
            for (int q = 0; q < 8; q++) in |= (mb[q] == (unsigned short)j);
            float mv = in ? g_avg[j] : 0.f;
            out[baseS + j] = in ? 1.f : 0.f;
            out[baseM + j] = mv;
        }
    } else if (b < 8192) {
        int k = b - 4096;
        if (k >= K) return;
        int c = g_sel[k];
        int sz = g_usz[c];
        float acc = 0.f;
        for (int mi = 0; mi < sz; mi++) {
            int m = g_uniq[c][mi];
            acc += g_avg[m] * x[(size_t)m * D_FEAT + t];
        }
        out[offX + (size_t)k * D_FEAT + t] = acc;
    } else {
        int i = (b - 8192) * 256 + t;
        out[offE + i] = (float)ei[i];
    }
}

// ------------------------- launch -------------------------
extern "C" void kernel_launch(void* const* d_in, const int* in_sizes, int n_in,
                              void* d_out, int out_size) {
    const float* x  = (const float*)d_in[0];
    const int*   ei = (const int*)d_in[1];
    float*       out = (float*)d_out;
    cudaStream_t st = cudaStreamPerThread;

    cudaFuncSetAttribute(k_sort_dedup, cudaFuncAttributeMaxDynamicSharedMemorySize, 65536);
    cudaFuncSetAttribute(k_greedy, cudaFuncAttributeMaxDynamicSharedMemorySize, G_SMEM_TOT);
    cudaFuncSetAttribute(k_c2, cudaFuncAttributeMaxDynamicSharedMemorySize, 49184);

    k_init       <<<16, 256, 0, st>>>();
    k_dist       <<<N_EDGES / 8, 256, 0, st>>>(x, ei);
    k_scan4096   <<<1, 1024, 0, st>>>(0);            // deg -> rowptr
    k_norm_fill  <<<N_EDGES / 256, 256, 0, st>>>(ei);
    k_avg        <<<16, 256, 0, st>>>();
    k_grow       <<<512, 256, 0, st>>>();
    k_sort_dedup <<<1, 1024, 65536, st>>>();
    k_greedy     <<<1, 256, G_SMEM_TOT, st>>>();
    k_c2         <<<1, 1024, 49184, st>>>();
    k_clearB     <<<512, 256, 0, st>>>();
    k_markB      <<<N_EDGES / 256, 256, 0, st>>>(ei);
    k_rowcnt     <<<512, 256, 0, st>>>();
    k_scan4096   <<<1, 1024, 0, st>>>(1);            // rn -> roff
    k_write_edges<<<512, 256, 0, st>>>(out);
    k_outputs    <<<8704, 256, 0, st>>>(x, ei, out);
}